// round 2
// baseline (speedup 1.0000x reference)
#include <cuda_runtime.h>
#include <cstdint>

// LocalPoolPointnetPPFusion: B=8, T=8192, H=128, C=128, R=128, NB=5
// fp32 baseline: fused resblock GEMMs + scatter-max pooling + plane means.

// ------------------------- scratch ( __device__ globals ) -------------------
__device__ float    g_net256 [16777216];   // [65536,256] geo stream input
__device__ float    g_netc256[16777216];   // [65536,256] corr stream input
__device__ float    g_net    [ 8388608];   // [65536,128] current net
__device__ float    g_pooled [ 8388608];   // [65536,128]
__device__ float    g_cgeo   [ 8388608];   // [65536,128]
__device__ float    g_ccorr  [ 8388608];   // [65536,128]
__device__ unsigned g_bins   [50331648];   // 3 * 8 * 16384 * 128 (keys or f32 sums)
__device__ float    g_cnt    [  393216];   // 3 * 8 * 16384
__device__ int      g_idx    [  196608];   // 3 * 65536

__device__ __forceinline__ float* bufptr(int sel) {
    switch (sel) {
        case 0:  return g_net256;
        case 1:  return g_netc256;
        case 2:  return g_net;
        case 3:  return g_pooled;
        case 4:  return g_cgeo;
        default: return g_ccorr;
    }
}

// monotone float <-> unsigned order map; key 0 is below every scattered value
__device__ __forceinline__ unsigned f2ord(float f) {
    unsigned u = __float_as_uint(f);
    return (u & 0x80000000u) ? ~u : (u | 0x80000000u);
}
__device__ __forceinline__ float ord2f(unsigned k) {
    return (k & 0x80000000u) ? __uint_as_float(k ^ 0x80000000u)
                             : __uint_as_float(~k);
}

// ------------------------- index computation --------------------------------
__global__ void k_idx(const float* __restrict__ p) {
    int m = blockIdx.x * 256 + threadIdx.x;              // 256 blocks -> 65536
    float x = p[3 * m + 0], y = p[3 * m + 1], z = p[3 * m + 2];
    float nx = fminf(fmaxf(__fadd_rn(__fdiv_rn(x, 1.001f), 0.5f), 0.0f), 0.999f);
    float ny = fminf(fmaxf(__fadd_rn(__fdiv_rn(y, 1.001f), 0.5f), 0.0f), 0.999f);
    float nz = fminf(fmaxf(__fadd_rn(__fdiv_rn(z, 1.001f), 0.5f), 0.0f), 0.999f);
    int gx = (int)floorf(__fmul_rn(nx, 128.0f));
    int gy = (int)floorf(__fmul_rn(ny, 128.0f));
    int gz = (int)floorf(__fmul_rn(nz, 128.0f));
    g_idx[m]          = gx + 128 * gz;   // plane 0: (0,2) xz
    g_idx[65536 + m]  = gx + 128 * gy;   // plane 1: (0,1) xy
    g_idx[131072 + m] = gy + 128 * gz;   // plane 2: (1,2) yz
}

// ------------------------- initial projections ------------------------------
__global__ void k_layer0(const float* __restrict__ p,  const float* __restrict__ p2,
                         const float* __restrict__ wp, const float* __restrict__ bp,
                         const float* __restrict__ wp2,const float* __restrict__ bp2) {
    int m = blockIdx.x, j = threadIdx.x;                 // 65536 x 256
    float a0 = p[3 * m], a1 = p[3 * m + 1], a2 = p[3 * m + 2];
    float q0 = p2[3 * m], q1 = p2[3 * m + 1], q2 = p2[3 * m + 2];
    float v  = fmaf(a0, wp[j],  fmaf(a1, wp[256 + j],  fmaf(a2, wp[512 + j],  bp[j])));
    float v2 = fmaf(q0, wp2[j], fmaf(q1, wp2[256 + j], fmaf(q2, wp2[512 + j], bp2[j])));
    g_net256 [(size_t)m * 256 + j] = v;
    g_netc256[(size_t)m * 256 + j] = v + v2;
}

// ------------------------- fused ResNet block -------------------------------
// out = x@ws + relu( relu(x)@w0 + b0 )@w1 + b1   (x is [A 128 cols | B 128 cols])
// 128 threads; 64 rows x 128 cols per CTA; 8x8 register micro-tile.
__global__ void __launch_bounds__(128)
k_resblock(int selA, int ldA, int offA, int selB, int ldB, int offB,
           const float* __restrict__ w0, const float* __restrict__ b0,
           const float* __restrict__ w1, const float* __restrict__ b1,
           const float* __restrict__ ws) {
    __shared__ float smem[12288];          // 48 KB
    float* sx    = smem;                   // [32][68]  (stage A x chunk, transposed)
    float* swA   = smem + 2176;            // [2][32][128] w0|ws chunk
    float* srelu = smem;                   // [64][128] stage B input
    float* swB   = smem + 8192;            // [32][128] w1 chunk

    const int tid = threadIdx.x;
    const int tx  = tid & 15;              // 16 col groups of 8
    const int ty  = tid >> 4;              // 8 row groups of 8
    const size_t m0 = (size_t)blockIdx.x * 64;

    const float* xA = bufptr(selA) + offA;
    const float* xB = bufptr(selB) + offB;

    float accN[8][8], accS[8][8];
#pragma unroll
    for (int i = 0; i < 8; i++)
#pragma unroll
        for (int j = 0; j < 8; j++) { accN[i][j] = 0.0f; accS[i][j] = 0.0f; }

    // ---- stage A: K = 256 over x ----
    for (int kc = 0; kc < 256; kc += 32) {
        __syncthreads();
        for (int i = tid; i < 32 * 64; i += 128) {
            int k = i & 31, r = i >> 5;
            int kg = kc + k;
            const float* src = (kg < 128) ? (xA + (m0 + r) * ldA + kg)
                                          : (xB + (m0 + r) * ldB + (kg - 128));
            sx[k * 68 + r] = *src;
        }
        for (int i = tid; i < 2048; i += 128) {
            int which = i >> 10;
            int j = i & 1023;
            int r = j >> 5, c4 = j & 31;
            const float* src = (which ? ws : w0) + (size_t)(kc + r) * 128 + c4 * 4;
            *(float4*)&swA[which * 4096 + r * 128 + c4 * 4] = *(const float4*)src;
        }
        __syncthreads();
#pragma unroll 4
        for (int kk = 0; kk < 32; kk++) {
            float xv[8];
            {
                float4 t0 = *(const float4*)&sx[kk * 68 + ty * 8];
                float4 t1 = *(const float4*)&sx[kk * 68 + ty * 8 + 4];
                xv[0]=t0.x; xv[1]=t0.y; xv[2]=t0.z; xv[3]=t0.w;
                xv[4]=t1.x; xv[5]=t1.y; xv[6]=t1.z; xv[7]=t1.w;
            }
            float w0v[8], wsv[8];
            {
                float4 a = *(const float4*)&swA[kk * 128 + tx * 8];
                float4 b = *(const float4*)&swA[kk * 128 + tx * 8 + 4];
                w0v[0]=a.x; w0v[1]=a.y; w0v[2]=a.z; w0v[3]=a.w;
                w0v[4]=b.x; w0v[5]=b.y; w0v[6]=b.z; w0v[7]=b.w;
                float4 c = *(const float4*)&swA[4096 + kk * 128 + tx * 8];
                float4 d = *(const float4*)&swA[4096 + kk * 128 + tx * 8 + 4];
                wsv[0]=c.x; wsv[1]=c.y; wsv[2]=c.z; wsv[3]=c.w;
                wsv[4]=d.x; wsv[5]=d.y; wsv[6]=d.z; wsv[7]=d.w;
            }
#pragma unroll
            for (int i = 0; i < 8; i++) {
                float xr = fmaxf(xv[i], 0.0f);
#pragma unroll
                for (int j = 0; j < 8; j++) {
                    accN[i][j] = fmaf(xr,    w0v[j], accN[i][j]);
                    accS[i][j] = fmaf(xv[i], wsv[j], accS[i][j]);
                }
            }
        }
    }

    // stash relu(accN + b0) into srelu[64][128]
    __syncthreads();
    {
        float b0v[8];
#pragma unroll
        for (int j = 0; j < 8; j++) b0v[j] = b0[tx * 8 + j];
#pragma unroll
        for (int i = 0; i < 8; i++) {
            float4 v0, v1;
            v0.x = fmaxf(accN[i][0] + b0v[0], 0.0f);
            v0.y = fmaxf(accN[i][1] + b0v[1], 0.0f);
            v0.z = fmaxf(accN[i][2] + b0v[2], 0.0f);
            v0.w = fmaxf(accN[i][3] + b0v[3], 0.0f);
            v1.x = fmaxf(accN[i][4] + b0v[4], 0.0f);
            v1.y = fmaxf(accN[i][5] + b0v[5], 0.0f);
            v1.z = fmaxf(accN[i][6] + b0v[6], 0.0f);
            v1.w = fmaxf(accN[i][7] + b0v[7], 0.0f);
            *(float4*)&srelu[(ty * 8 + i) * 128 + tx * 8]     = v0;
            *(float4*)&srelu[(ty * 8 + i) * 128 + tx * 8 + 4] = v1;
        }
    }

    // ---- stage B: K = 128 over relu(net1) ----
    for (int kc = 0; kc < 128; kc += 32) {
        __syncthreads();
        for (int i = tid; i < 1024; i += 128) {
            int r = i >> 5, c4 = i & 31;
            *(float4*)&swB[r * 128 + c4 * 4] =
                *(const float4*)(w1 + (size_t)(kc + r) * 128 + c4 * 4);
        }
        __syncthreads();
#pragma unroll 4
        for (int kk = 0; kk < 32; kk++) {
            float xv[8];
#pragma unroll
            for (int i = 0; i < 8; i++) xv[i] = srelu[(ty * 8 + i) * 128 + kc + kk];
            float wv[8];
            {
                float4 a = *(const float4*)&swB[kk * 128 + tx * 8];
                float4 b = *(const float4*)&swB[kk * 128 + tx * 8 + 4];
                wv[0]=a.x; wv[1]=a.y; wv[2]=a.z; wv[3]=a.w;
                wv[4]=b.x; wv[5]=b.y; wv[6]=b.z; wv[7]=b.w;
            }
#pragma unroll
            for (int i = 0; i < 8; i++)
#pragma unroll
                for (int j = 0; j < 8; j++)
                    accS[i][j] = fmaf(xv[i], wv[j], accS[i][j]);
        }
    }

    // out = accS + b1 -> g_net
    {
        float b1v[8];
#pragma unroll
        for (int j = 0; j < 8; j++) b1v[j] = b1[tx * 8 + j];
#pragma unroll
        for (int i = 0; i < 8; i++) {
            float4 v0, v1;
            v0.x = accS[i][0] + b1v[0]; v0.y = accS[i][1] + b1v[1];
            v0.z = accS[i][2] + b1v[2]; v0.w = accS[i][3] + b1v[3];
            v1.x = accS[i][4] + b1v[4]; v1.y = accS[i][5] + b1v[5];
            v1.z = accS[i][6] + b1v[6]; v1.w = accS[i][7] + b1v[7];
            size_t row = m0 + ty * 8 + i;
            *(float4*)&g_net[row * 128 + tx * 8]     = v0;
            *(float4*)&g_net[row * 128 + tx * 8 + 4] = v1;
        }
    }
}

// ------------------------- final fc (K=128) ---------------------------------
__global__ void __launch_bounds__(128)
k_gemm128(int selx, const float* __restrict__ w, const float* __restrict__ b, int selo) {
    __shared__ float smem[6272];           // sx 2176 + sw 4096
    float* sx = smem;
    float* sw = smem + 2176;
    const int tid = threadIdx.x;
    const int tx = tid & 15, ty = tid >> 4;
    const size_t m0 = (size_t)blockIdx.x * 64;
    const float* x = bufptr(selx);
    float* out = bufptr(selo);

    float acc[8][8];
#pragma unroll
    for (int i = 0; i < 8; i++)
#pragma unroll
        for (int j = 0; j < 8; j++) acc[i][j] = 0.0f;

    for (int kc = 0; kc < 128; kc += 32) {
        __syncthreads();
        for (int i = tid; i < 32 * 64; i += 128) {
            int k = i & 31, r = i >> 5;
            sx[k * 68 + r] = x[(m0 + r) * 128 + kc + k];
        }
        for (int i = tid; i < 1024; i += 128) {
            int r = i >> 5, c4 = i & 31;
            *(float4*)&sw[r * 128 + c4 * 4] =
                *(const float4*)(w + (size_t)(kc + r) * 128 + c4 * 4);
        }
        __syncthreads();
#pragma unroll 4
        for (int kk = 0; kk < 32; kk++) {
            float xv[8];
            {
                float4 t0 = *(const float4*)&sx[kk * 68 + ty * 8];
                float4 t1 = *(const float4*)&sx[kk * 68 + ty * 8 + 4];
                xv[0]=t0.x; xv[1]=t0.y; xv[2]=t0.z; xv[3]=t0.w;
                xv[4]=t1.x; xv[5]=t1.y; xv[6]=t1.z; xv[7]=t1.w;
            }
            float wv[8];
            {
                float4 a = *(const float4*)&sw[kk * 128 + tx * 8];
                float4 bq = *(const float4*)&sw[kk * 128 + tx * 8 + 4];
                wv[0]=a.x; wv[1]=a.y; wv[2]=a.z; wv[3]=a.w;
                wv[4]=bq.x; wv[5]=bq.y; wv[6]=bq.z; wv[7]=bq.w;
            }
#pragma unroll
            for (int i = 0; i < 8; i++)
#pragma unroll
                for (int j = 0; j < 8; j++)
                    acc[i][j] = fmaf(xv[i], wv[j], acc[i][j]);
        }
    }
    {
        float bv[8];
#pragma unroll
        for (int j = 0; j < 8; j++) bv[j] = b[tx * 8 + j];
#pragma unroll
        for (int i = 0; i < 8; i++) {
            float4 v0, v1;
            v0.x = acc[i][0] + bv[0]; v0.y = acc[i][1] + bv[1];
            v0.z = acc[i][2] + bv[2]; v0.w = acc[i][3] + bv[3];
            v1.x = acc[i][4] + bv[4]; v1.y = acc[i][5] + bv[5];
            v1.z = acc[i][6] + bv[6]; v1.w = acc[i][7] + bv[7];
            size_t row = m0 + ty * 8 + i;
            *(float4*)&out[row * 128 + tx * 8]     = v0;
            *(float4*)&out[row * 128 + tx * 8 + 4] = v1;
        }
    }
}

// ------------------------- pooling / plane reductions -----------------------
__global__ void k_clear_bins() {
    size_t i = (size_t)blockIdx.x * 256 + threadIdx.x;   // 49152 blocks of uint4
    ((uint4*)g_bins)[i] = make_uint4(0u, 0u, 0u, 0u);
}

__global__ void k_clear_cnt() {
    int i = blockIdx.x * 256 + threadIdx.x;              // 1536 blocks
    g_cnt[i] = 0.0f;
}

__global__ void k_scatter_max() {
    int m = blockIdx.x, c = threadIdx.x;                 // 65536 x 128
    int b = m >> 13;
    unsigned key = f2ord(g_net[(size_t)m * 128 + c]);
#pragma unroll
    for (int p = 0; p < 3; p++) {
        int bin = g_idx[p * 65536 + m];
        atomicMax(&g_bins[((size_t)p * 131072 + b * 16384 + bin) * 128 + c], key);
    }
}

__global__ void k_gather() {
    int m = blockIdx.x, c = threadIdx.x;
    int b = m >> 13;
    float s = 0.0f;
#pragma unroll
    for (int p = 0; p < 3; p++) {
        int bin = g_idx[p * 65536 + m];
        unsigned k = g_bins[((size_t)p * 131072 + b * 16384 + bin) * 128 + c];
        if (k) s += ord2f(k);
    }
    g_pooled[(size_t)m * 128 + c] = s;
}

__global__ void k_scatter_sum(int sel, int do_count) {
    int m = blockIdx.x, c = threadIdx.x;
    int b = m >> 13;
    float v = bufptr(sel)[(size_t)m * 128 + c];
    float* sums = (float*)g_bins;
#pragma unroll
    for (int p = 0; p < 3; p++) {
        int bin = g_idx[p * 65536 + m];
        atomicAdd(&sums[((size_t)p * 131072 + b * 16384 + bin) * 128 + c], v);
        if (do_count && c == 0)
            atomicAdd(&g_cnt[p * 131072 + b * 16384 + bin], 1.0f);
    }
}

// sums [p][b][bin][c] -> out [p+po][b][c][bin] / max(cnt,1)
__global__ void k_transpose_div(float* __restrict__ outb, int po) {
    __shared__ float t[32][33];
    int p = blockIdx.z >> 3, b = blockIdx.z & 7;         // grid.z = 24
    int bin0 = blockIdx.x * 32, c0 = blockIdx.y * 32;    // grid (512, 4, 24), blk (32,8)
    const float* sums = (const float*)g_bins;
    size_t base = (size_t)p * 131072 + (size_t)b * 16384;
#pragma unroll
    for (int i = 0; i < 4; i++)
        t[threadIdx.y + 8 * i][threadIdx.x] =
            sums[(base + bin0 + threadIdx.y + 8 * i) * 128 + c0 + threadIdx.x];
    __syncthreads();
    float cv = fmaxf(g_cnt[base + bin0 + threadIdx.x], 1.0f);
#pragma unroll
    for (int i = 0; i < 4; i++) {
        int c = c0 + threadIdx.y + 8 * i;
        outb[(((size_t)(p + po) * 8 + b) * 128 + c) * 16384 + bin0 + threadIdx.x] =
            t[threadIdx.x][threadIdx.y + 8 * i] / cv;
    }
}

// ------------------------- driver -------------------------------------------
static void run_stream(int sel256,
                       const float* w0, const float* b0,
                       const float* w1, const float* b1, const float* ws,
                       const float* fcw, const float* fcb, int selout) {
    k_resblock<<<1024, 128>>>(sel256, 256, 0, sel256, 256, 128,
                              w0, b0, w1, b1, ws);
    for (int i = 1; i < 5; i++) {
        k_clear_bins<<<49152, 256>>>();
        k_scatter_max<<<65536, 128>>>();
        k_gather<<<65536, 128>>>();
        k_resblock<<<1024, 128>>>(2, 128, 0, 3, 128, 0,
                                  w0 + (size_t)i * 32768, b0 + i * 128,
                                  w1 + (size_t)i * 16384, b1 + i * 128,
                                  ws + (size_t)i * 32768);
    }
    k_gemm128<<<1024, 128>>>(2, fcw, fcb, selout);
}

extern "C" void kernel_launch(void* const* d_in, const int* in_sizes, int n_in,
                              void* d_out, int out_size) {
    const float* p      = (const float*)d_in[0];
    const float* p2     = (const float*)d_in[1];
    const float* wp     = (const float*)d_in[2];
    const float* bp     = (const float*)d_in[3];
    const float* wp2    = (const float*)d_in[4];
    const float* bp2    = (const float*)d_in[5];
    const float* blk_w0 = (const float*)d_in[6];
    const float* blk_b0 = (const float*)d_in[7];
    const float* blk_w1 = (const float*)d_in[8];
    const float* blk_b1 = (const float*)d_in[9];
    const float* blk_ws = (const float*)d_in[10];
    const float* blkc_w0= (const float*)d_in[11];
    const float* blkc_b0= (const float*)d_in[12];
    const float* blkc_w1= (const float*)d_in[13];
    const float* blkc_b1= (const float*)d_in[14];
    const float* blkc_ws= (const float*)d_in[15];
    const float* fc_c_w = (const float*)d_in[16];
    const float* fc_c_b = (const float*)d_in[17];
    const float* fc_cc_w= (const float*)d_in[18];
    const float* fc_cc_b= (const float*)d_in[19];
    float* out = (float*)d_out;

    k_idx<<<256, 256>>>(p);
    k_layer0<<<65536, 256>>>(p, p2, wp, bp, wp2, bp2);

    run_stream(0, blk_w0,  blk_b0,  blk_w1,  blk_b1,  blk_ws,  fc_c_w,  fc_c_b,  4);
    run_stream(1, blkc_w0, blkc_b0, blkc_w1, blkc_b1, blkc_ws, fc_cc_w, fc_cc_b, 5);

    // plane means: geo (with counts), then corr (reuses counts)
    k_clear_bins<<<49152, 256>>>();
    k_clear_cnt<<<1536, 256>>>();
    k_scatter_sum<<<65536, 128>>>(4, 1);
    k_transpose_div<<<dim3(512, 4, 24), dim3(32, 8)>>>(out, 0);
    k_clear_bins<<<49152, 256>>>();
    k_scatter_sum<<<65536, 128>>>(5, 0);
    k_transpose_div<<<dim3(512, 4, 24), dim3(32, 8)>>>(out, 3);
}

// round 7
// speedup vs baseline: 2.1425x; 2.1425x over previous
#include <cuda_runtime.h>
#include <cuda_bf16.h>
#include <cstdint>

// LocalPoolPointnetPPFusion: B=8, T=8192, H=128, C=128, R=128, NB=5
// mma.sync bf16 hi/lo (3-product) GEMMs, static-smem only (<=48KB, no host
// API besides kernel launches) + scatter-max pooling + plane means.

// ------------------------- scratch ( __device__ globals ) -------------------
__device__ float    g_net256 [16777216];   // [65536,256] geo stream input
__device__ float    g_netc256[16777216];   // [65536,256] corr stream input
__device__ float    g_net    [ 8388608];   // [65536,128] current net
__device__ float    g_pooled [ 8388608];   // [65536,128]
__device__ float    g_cgeo   [ 8388608];   // [65536,128]
__device__ float    g_ccorr  [ 8388608];   // [65536,128]
__device__ unsigned g_bins   [50331648];   // 3 * 8 * 16384 * 128
__device__ float    g_cnt    [  393216];   // 3 * 8 * 16384
__device__ int      g_idx    [  196608];   // 3 * 65536
__device__ __align__(16) __nv_bfloat16 g_wt[1703936];  // transposed h/l weights

__device__ __forceinline__ float* bufptr(int sel) {
    switch (sel) {
        case 0:  return g_net256;
        case 1:  return g_netc256;
        case 2:  return g_net;
        case 3:  return g_pooled;
        case 4:  return g_cgeo;
        default: return g_ccorr;
    }
}

__device__ __forceinline__ unsigned f2ord(float f) {
    unsigned u = __float_as_uint(f);
    return (u & 0x80000000u) ? ~u : (u | 0x80000000u);
}
__device__ __forceinline__ float ord2f(unsigned k) {
    return (k & 0x80000000u) ? __uint_as_float(k ^ 0x80000000u)
                             : __uint_as_float(~k);
}

__device__ __forceinline__ uint32_t smem_u32(const void* p) {
    uint32_t a;
    asm("{ .reg .u64 t; cvta.to.shared.u64 t, %1; cvt.u32.u64 %0, t; }"
        : "=r"(a) : "l"(p));
    return a;
}

#define LDSM4(r0, r1, r2, r3, addr)                                         \
    asm volatile("ldmatrix.sync.aligned.m8n8.x4.shared.b16 {%0,%1,%2,%3}, [%4];" \
                 : "=r"(r0), "=r"(r1), "=r"(r2), "=r"(r3) : "r"(addr))
#define LDSM2(r0, r1, addr)                                                 \
    asm volatile("ldmatrix.sync.aligned.m8n8.x2.shared.b16 {%0,%1}, [%2];"  \
                 : "=r"(r0), "=r"(r1) : "r"(addr))
#define MMA16816(c, a0, a1, a2, a3, b0, b1)                                 \
    asm volatile("mma.sync.aligned.m16n8k16.row.col.f32.bf16.bf16.f32 "     \
                 "{%0,%1,%2,%3}, {%4,%5,%6,%7}, {%8,%9}, {%0,%1,%2,%3};"    \
                 : "+f"((c)[0]), "+f"((c)[1]), "+f"((c)[2]), "+f"((c)[3])   \
                 : "r"(a0), "r"(a1), "r"(a2), "r"(a3), "r"(b0), "r"(b1))

__device__ __forceinline__ void split_hl(float v, __nv_bfloat16& h, __nv_bfloat16& l) {
    h = __float2bfloat16_rn(v);
    l = __float2bfloat16_rn(v - __bfloat162float(h));
}

// zero bf16 lanes of (h,l) where h's sign bit is set: exact relu h/l split.
__device__ __forceinline__ void relu_mask(uint32_t h, uint32_t l,
                                          uint32_t& rh, uint32_t& rl) {
    uint32_t t  = (h >> 15) & 0x00010001u;
    uint32_t zm = t * 0xFFFFu;
    rh = h & ~zm;
    rl = l & ~zm;
}

#define TST 40               // smem tile stride in bf16 elems (80B rows)

// ------------------------- index computation --------------------------------
__global__ void k_idx(const float* __restrict__ p) {
    int m = blockIdx.x * 256 + threadIdx.x;
    float x = p[3 * m + 0], y = p[3 * m + 1], z = p[3 * m + 2];
    float nx = fminf(fmaxf(__fadd_rn(__fdiv_rn(x, 1.001f), 0.5f), 0.0f), 0.999f);
    float ny = fminf(fmaxf(__fadd_rn(__fdiv_rn(y, 1.001f), 0.5f), 0.0f), 0.999f);
    float nz = fminf(fmaxf(__fadd_rn(__fdiv_rn(z, 1.001f), 0.5f), 0.0f), 0.999f);
    int gx = (int)floorf(__fmul_rn(nx, 128.0f));
    int gy = (int)floorf(__fmul_rn(ny, 128.0f));
    int gz = (int)floorf(__fmul_rn(nz, 128.0f));
    g_idx[m]          = gx + 128 * gz;
    g_idx[65536 + m]  = gx + 128 * gy;
    g_idx[131072 + m] = gy + 128 * gz;
}

// ------------------------- initial projections ------------------------------
__global__ void k_layer0(const float* __restrict__ p,  const float* __restrict__ p2,
                         const float* __restrict__ wp, const float* __restrict__ bp,
                         const float* __restrict__ wp2,const float* __restrict__ bp2) {
    int m = blockIdx.x, j = threadIdx.x;                 // 65536 x 256
    float a0 = p[3 * m], a1 = p[3 * m + 1], a2 = p[3 * m + 2];
    float q0 = p2[3 * m], q1 = p2[3 * m + 1], q2 = p2[3 * m + 2];
    float v  = fmaf(a0, wp[j],  fmaf(a1, wp[256 + j],  fmaf(a2, wp[512 + j],  bp[j])));
    float v2 = fmaf(q0, wp2[j], fmaf(q1, wp2[256 + j], fmaf(q2, wp2[512 + j], bp2[j])));
    g_net256 [(size_t)m * 256 + j] = v;
    g_netc256[(size_t)m * 256 + j] = v + v2;
}

// ------------------------- weight prep: transpose + h/l split ---------------
// w is [K][128] row-major; write wT_h [128][K] at g_wt[ooff], wT_l at +128*K.
__global__ void k_prep(const float* __restrict__ w, int K, int ooff) {
    int k = blockIdx.x * 128 + threadIdx.x;
    int n = blockIdx.y;
    float v = w[(size_t)k * 128 + n];
    __nv_bfloat16 h, l;
    split_hl(v, h, l);
    g_wt[ooff + (size_t)n * K + k] = h;
    g_wt[ooff + 128 * K + (size_t)n * K + k] = l;
}

// ------------------------- fused ResNet block (mma.sync) --------------------
// out = x@ws + relu( relu(x)@w0 + b0 )@w1 + b1,  x = [A 128 | B 128] cols.
// CTA: 512 threads = 16 warps; M-tile 128; warp tile m16 x n64.
// Static smem: 4 slots [128][40] bf16 = 40960 B. K chunked at 32.
// Stage A two-passes the weight slot (w0 then ws) per chunk, x frags kept in
// registers. relu h/l frags derived from x frags by sign-masking (exact).
__global__ void __launch_bounds__(512)
k_resblock_mma(int selA, int ldA, int offA, int selB, int ldB, int offB,
               int woff, const float* __restrict__ b0, const float* __restrict__ b1)
{
    __shared__ __nv_bfloat16 sXh[128 * TST], sXl[128 * TST];
    __shared__ __nv_bfloat16 sWh[128 * TST], sWl[128 * TST];
    const uint32_t aXh = smem_u32(sXh), aXl = smem_u32(sXl);
    const uint32_t aWh = smem_u32(sWh), aWl = smem_u32(sWl);

    const int tid = threadIdx.x, wid = tid >> 5, lane = tid & 31;
    const int wm = (wid >> 1) * 16;            // warp row base (0..112)
    const int wn = (wid & 1) * 64;             // warp col base (0 or 64)
    const size_t m0 = (size_t)blockIdx.x * 128;

    const float* xA = bufptr(selA) + offA;
    const float* xB = bufptr(selB) + offB;
    const __nv_bfloat16* w0h = g_wt + woff;          // [128][256]
    const __nv_bfloat16* w0l = w0h + 32768;
    const __nv_bfloat16* wsh = w0h + 65536;
    const __nv_bfloat16* wsl = w0h + 98304;
    const __nv_bfloat16* w1h = w0h + 131072;         // [128][128]
    const __nv_bfloat16* w1l = w0h + 147456;

    float accN[32], accS[32];
#pragma unroll
    for (int i = 0; i < 32; i++) { accN[i] = 0.0f; accS[i] = 0.0f; }

    const uint32_t akOff = (uint32_t)((wm + (lane & 15)) * TST + ((lane >> 4) & 1) * 8) * 2;
    const uint32_t bkOff = (uint32_t)((wn + (lane & 7)) * TST + ((lane >> 3) & 1) * 8) * 2;
    const int wn_ = tid >> 2, wq_ = tid & 3;   // weight-chunk copy indices

    // ---------------- stage A: K = 256, 8 chunks of 32 ----------------------
    for (int kc = 0; kc < 256; kc += 32) {
        const float* xS = (kc < 128) ? xA : xB;
        const int ldS   = (kc < 128) ? ldA : ldB;
        const int cb    = kc & 127;
        __syncthreads();
#pragma unroll
        for (int it = 0; it < 4; it++) {       // x chunk: 128 rows x 16 pairs
            int e = it * 512 + tid;
            int r = e >> 4, cp = e & 15;
            float2 v = *(const float2*)&xS[(m0 + r) * ldS + cb + cp * 2];
            __nv_bfloat162 h2, l2;
            split_hl(v.x, h2.x, l2.x);
            split_hl(v.y, h2.y, l2.y);
            int o = r * TST + cp * 2;
            *(__nv_bfloat162*)&sXh[o] = h2;
            *(__nv_bfloat162*)&sXl[o] = l2;
        }
        *(uint4*)&sWh[wn_ * TST + wq_ * 8] = *(const uint4*)&w0h[(size_t)wn_ * 256 + kc + wq_ * 8];
        *(uint4*)&sWl[wn_ * TST + wq_ * 8] = *(const uint4*)&w0l[(size_t)wn_ * 256 + kc + wq_ * 8];
        __syncthreads();

        uint32_t fxh[2][4], fxl[2][4];
#pragma unroll
        for (int ks = 0; ks < 2; ks++) {       // accN pass: relu(x) @ w0
            LDSM4(fxh[ks][0], fxh[ks][1], fxh[ks][2], fxh[ks][3], aXh + akOff + ks * 32);
            LDSM4(fxl[ks][0], fxl[ks][1], fxl[ks][2], fxl[ks][3], aXl + akOff + ks * 32);
            uint32_t frh[4], frl[4];
#pragma unroll
            for (int i = 0; i < 4; i++) relu_mask(fxh[ks][i], fxl[ks][i], frh[i], frl[i]);
#pragma unroll
            for (int jn = 0; jn < 8; jn++) {
                uint32_t ba = bkOff + ks * 32 + jn * (8 * TST * 2);
                uint32_t p0, p1, q0, q1;
                LDSM2(p0, p1, aWh + ba);
                LDSM2(q0, q1, aWl + ba);
                MMA16816(accN + jn * 4, frh[0], frh[1], frh[2], frh[3], p0, p1);
                MMA16816(accN + jn * 4, frh[0], frh[1], frh[2], frh[3], q0, q1);
                MMA16816(accN + jn * 4, frl[0], frl[1], frl[2], frl[3], p0, p1);
            }
        }
        __syncthreads();
        *(uint4*)&sWh[wn_ * TST + wq_ * 8] = *(const uint4*)&wsh[(size_t)wn_ * 256 + kc + wq_ * 8];
        *(uint4*)&sWl[wn_ * TST + wq_ * 8] = *(const uint4*)&wsl[(size_t)wn_ * 256 + kc + wq_ * 8];
        __syncthreads();
#pragma unroll
        for (int ks = 0; ks < 2; ks++) {       // accS pass: x @ ws
#pragma unroll
            for (int jn = 0; jn < 8; jn++) {
                uint32_t ba = bkOff + ks * 32 + jn * (8 * TST * 2);
                uint32_t p0, p1, q0, q1;
                LDSM2(p0, p1, aWh + ba);
                LDSM2(q0, q1, aWl + ba);
                MMA16816(accS + jn * 4, fxh[ks][0], fxh[ks][1], fxh[ks][2], fxh[ks][3], p0, p1);
                MMA16816(accS + jn * 4, fxh[ks][0], fxh[ks][1], fxh[ks][2], fxh[ks][3], q0, q1);
                MMA16816(accS + jn * 4, fxl[ks][0], fxl[ks][1], fxl[ks][2], fxl[ks][3], p0, p1);
            }
        }
    }

    // ---------------- stage B: K = 128, 4 chunks of 32 ----------------------
    // srelu chunk written from accN regs by the owning warps; w1 chunk loaded;
    // then MMA into accS.
    for (int kb = 0; kb < 4; kb++) {
        __syncthreads();
        if (wn == (kb >> 1) * 64) {
            int row0 = wm + (lane >> 2);
#pragma unroll
            for (int jj = 0; jj < 4; jj++) {
                int jn = (kb & 1) * 4 + jj;
                int c  = wn + (lane & 3) * 2 + jn * 8;
                int lc = jj * 8 + (lane & 3) * 2;
                float bv0 = b0[c], bv1 = b0[c + 1];
                float v00 = fmaxf(accN[jn * 4 + 0] + bv0, 0.0f);
                float v01 = fmaxf(accN[jn * 4 + 1] + bv1, 0.0f);
                float v10 = fmaxf(accN[jn * 4 + 2] + bv0, 0.0f);
                float v11 = fmaxf(accN[jn * 4 + 3] + bv1, 0.0f);
                __nv_bfloat162 h2, l2;
                split_hl(v00, h2.x, l2.x); split_hl(v01, h2.y, l2.y);
                *(__nv_bfloat162*)&sXh[row0 * TST + lc] = h2;
                *(__nv_bfloat162*)&sXl[row0 * TST + lc] = l2;
                split_hl(v10, h2.x, l2.x); split_hl(v11, h2.y, l2.y);
                *(__nv_bfloat162*)&sXh[(row0 + 8) * TST + lc] = h2;
                *(__nv_bfloat162*)&sXl[(row0 + 8) * TST + lc] = l2;
            }
        }
        *(uint4*)&sWh[wn_ * TST + wq_ * 8] = *(const uint4*)&w1h[(size_t)wn_ * 128 + kb * 32 + wq_ * 8];
        *(uint4*)&sWl[wn_ * TST + wq_ * 8] = *(const uint4*)&w1l[(size_t)wn_ * 128 + kb * 32 + wq_ * 8];
        __syncthreads();
#pragma unroll
        for (int ks = 0; ks < 2; ks++) {
            uint32_t fh[4], fl[4];
            LDSM4(fh[0], fh[1], fh[2], fh[3], aXh + akOff + ks * 32);
            LDSM4(fl[0], fl[1], fl[2], fl[3], aXl + akOff + ks * 32);
#pragma unroll
            for (int jn = 0; jn < 8; jn++) {
                uint32_t ba = bkOff + ks * 32 + jn * (8 * TST * 2);
                uint32_t p0, p1, q0, q1;
                LDSM2(p0, p1, aWh + ba);
                LDSM2(q0, q1, aWl + ba);
                MMA16816(accS + jn * 4, fh[0], fh[1], fh[2], fh[3], p0, p1);
                MMA16816(accS + jn * 4, fh[0], fh[1], fh[2], fh[3], q0, q1);
                MMA16816(accS + jn * 4, fl[0], fl[1], fl[2], fl[3], p0, p1);
            }
        }
    }

    // -------- epilogue: g_net = accS + b1 -----------------------------------
    {
        int row0 = wm + (lane >> 2);
        int cb2 = wn + (lane & 3) * 2;
#pragma unroll
        for (int jn = 0; jn < 8; jn++) {
            int c = cb2 + jn * 8;
            float bv0 = b1[c], bv1 = b1[c + 1];
            float2 v0 = make_float2(accS[jn * 4 + 0] + bv0, accS[jn * 4 + 1] + bv1);
            float2 v1 = make_float2(accS[jn * 4 + 2] + bv0, accS[jn * 4 + 3] + bv1);
            *(float2*)&g_net[(m0 + row0) * 128 + c]     = v0;
            *(float2*)&g_net[(m0 + row0 + 8) * 128 + c] = v1;
        }
    }
}

// ------------------------- final fc (mma.sync, K=128) -----------------------
__global__ void __launch_bounds__(512)
k_fc_mma(int selx, int woff, const float* __restrict__ b, int selo)
{
    __shared__ __nv_bfloat16 sXh[128 * TST], sXl[128 * TST];
    __shared__ __nv_bfloat16 sWh[128 * TST], sWl[128 * TST];
    const uint32_t aXh = smem_u32(sXh), aXl = smem_u32(sXl);
    const uint32_t aWh = smem_u32(sWh), aWl = smem_u32(sWl);

    const int tid = threadIdx.x, wid = tid >> 5, lane = tid & 31;
    const int wm = (wid >> 1) * 16;
    const int wn = (wid & 1) * 64;
    const size_t m0 = (size_t)blockIdx.x * 128;

    const float* x = bufptr(selx);
    const __nv_bfloat16* wh = g_wt + woff;   // [128][128]
    const __nv_bfloat16* wl = wh + 16384;

    float acc[32];
#pragma unroll
    for (int i = 0; i < 32; i++) acc[i] = 0.0f;

    const uint32_t akOff = (uint32_t)((wm + (lane & 15)) * TST + ((lane >> 4) & 1) * 8) * 2;
    const uint32_t bkOff = (uint32_t)((wn + (lane & 7)) * TST + ((lane >> 3) & 1) * 8) * 2;
    const int wn_ = tid >> 2, wq_ = tid & 3;

    for (int kc = 0; kc < 128; kc += 32) {
        __syncthreads();
#pragma unroll
        for (int it = 0; it < 4; it++) {
            int e = it * 512 + tid;
            int r = e >> 4, cp = e & 15;
            float2 v = *(const float2*)&x[(m0 + r) * 128 + kc + cp * 2];
            __nv_bfloat162 h2, l2;
            split_hl(v.x, h2.x, l2.x);
            split_hl(v.y, h2.y, l2.y);
            int o = r * TST + cp * 2;
            *(__nv_bfloat162*)&sXh[o] = h2;
            *(__nv_bfloat162*)&sXl[o] = l2;
        }
        *(uint4*)&sWh[wn_ * TST + wq_ * 8] = *(const uint4*)&wh[(size_t)wn_ * 128 + kc + wq_ * 8];
        *(uint4*)&sWl[wn_ * TST + wq_ * 8] = *(const uint4*)&wl[(size_t)wn_ * 128 + kc + wq_ * 8];
        __syncthreads();
#pragma unroll
        for (int ks = 0; ks < 2; ks++) {
            uint32_t fh[4], fl[4];
            LDSM4(fh[0], fh[1], fh[2], fh[3], aXh + akOff + ks * 32);
            LDSM4(fl[0], fl[1], fl[2], fl[3], aXl + akOff + ks * 32);
#pragma unroll
            for (int jn = 0; jn < 8; jn++) {
                uint32_t ba = bkOff + ks * 32 + jn * (8 * TST * 2);
                uint32_t p0, p1, q0, q1;
                LDSM2(p0, p1, aWh + ba);
                LDSM2(q0, q1, aWl + ba);
                MMA16816(acc + jn * 4, fh[0], fh[1], fh[2], fh[3], p0, p1);
                MMA16816(acc + jn * 4, fh[0], fh[1], fh[2], fh[3], q0, q1);
                MMA16816(acc + jn * 4, fl[0], fl[1], fl[2], fl[3], p0, p1);
            }
        }
    }

    {
        float* out = bufptr(selo);
        int row0 = wm + (lane >> 2);
        int cb2 = wn + (lane & 3) * 2;
#pragma unroll
        for (int jn = 0; jn < 8; jn++) {
            int c = cb2 + jn * 8;
            float bv0 = b[c], bv1 = b[c + 1];
            float2 v0 = make_float2(acc[jn * 4 + 0] + bv0, acc[jn * 4 + 1] + bv1);
            float2 v1 = make_float2(acc[jn * 4 + 2] + bv0, acc[jn * 4 + 3] + bv1);
            *(float2*)&out[(m0 + row0) * 128 + c]     = v0;
            *(float2*)&out[(m0 + row0 + 8) * 128 + c] = v1;
        }
    }
}

// ------------------------- pooling / plane reductions -----------------------
__global__ void k_clear_bins() {
    size_t i = (size_t)blockIdx.x * 256 + threadIdx.x;
    ((uint4*)g_bins)[i] = make_uint4(0u, 0u, 0u, 0u);
}
__global__ void k_clear_cnt() {
    int i = blockIdx.x * 256 + threadIdx.x;
    g_cnt[i] = 0.0f;
}
__global__ void k_scatter_max() {
    int m = blockIdx.x, c = threadIdx.x;
    int b = m >> 13;
    unsigned key = f2ord(g_net[(size_t)m * 128 + c]);
#pragma unroll
    for (int p = 0; p < 3; p++) {
        int bin = g_idx[p * 65536 + m];
        atomicMax(&g_bins[((size_t)p * 131072 + b * 16384 + bin) * 128 + c], key);
    }
}
__global__ void k_gather() {
    int m = blockIdx.x, c = threadIdx.x;
    int b = m >> 13;
    float s = 0.0f;
#pragma unroll
    for (int p = 0; p < 3; p++) {
        int bin = g_idx[p * 65536 + m];
        unsigned k = g_bins[((size_t)p * 131072 + b * 16384 + bin) * 128 + c];
        if (k) s += ord2f(k);
    }
    g_pooled[(size_t)m * 128 + c] = s;
}
__global__ void k_scatter_sum(int sel, int do_count) {
    int m = blockIdx.x, c = threadIdx.x;
    int b = m >> 13;
    float v = bufptr(sel)[(size_t)m * 128 + c];
    float* sums = (float*)g_bins;
#pragma unroll
    for (int p = 0; p < 3; p++) {
        int bin = g_idx[p * 65536 + m];
        atomicAdd(&sums[((size_t)p * 131072 + b * 16384 + bin) * 128 + c], v);
        if (do_count && c == 0)
            atomicAdd(&g_cnt[p * 131072 + b * 16384 + bin], 1.0f);
    }
}
__global__ void k_transpose_div(float* __restrict__ outb, int po) {
    __shared__ float t[32][33];
    int p = blockIdx.z >> 3, b = blockIdx.z & 7;
    int bin0 = blockIdx.x * 32, c0 = blockIdx.y * 32;
    const float* sums = (const float*)g_bins;
    size_t base = (size_t)p * 131072 + (size_t)b * 16384;
#pragma unroll
    for (int i = 0; i < 4; i++)
        t[threadIdx.y + 8 * i][threadIdx.x] =
            sums[(base + bin0 + threadIdx.y + 8 * i) * 128 + c0 + threadIdx.x];
    __syncthreads();
    float cv = fmaxf(g_cnt[base + bin0 + threadIdx.x], 1.0f);
#pragma unroll
    for (int i = 0; i < 4; i++) {
        int c = c0 + threadIdx.y + 8 * i;
        outb[(((size_t)(p + po) * 8 + b) * 128 + c) * 16384 + bin0 + threadIdx.x] =
            t[threadIdx.x][threadIdx.y + 8 * i] / cv;
    }
}

// ------------------------- driver -------------------------------------------
static inline int wt_off_blk(int s, int i) { return (s * 5 + i) * 163840; }

static void prep_stream(const float* w0, const float* w1, const float* ws,
                        const float* fcw, int s) {
    for (int i = 0; i < 5; i++) {
        int off = wt_off_blk(s, i);
        k_prep<<<dim3(2, 128), 128>>>(w0 + (size_t)i * 32768, 256, off);
        k_prep<<<dim3(2, 128), 128>>>(ws + (size_t)i * 32768, 256, off + 65536);
        k_prep<<<dim3(1, 128), 128>>>(w1 + (size_t)i * 16384, 128, off + 131072);
    }
    k_prep<<<dim3(1, 128), 128>>>(fcw, 128, 1638400 + s * 32768);
}

static void run_stream(int s, int sel256, const float* b0, const float* b1,
                       const float* fcb, int selout) {
    k_resblock_mma<<<512, 512>>>(sel256, 256, 0, sel256, 256, 128,
                                 wt_off_blk(s, 0), b0, b1);
    for (int i = 1; i < 5; i++) {
        k_clear_bins<<<49152, 256>>>();
        k_scatter_max<<<65536, 128>>>();
        k_gather<<<65536, 128>>>();
        k_resblock_mma<<<512, 512>>>(2, 128, 0, 3, 128, 0,
                                     wt_off_blk(s, i), b0 + i * 128, b1 + i * 128);
    }
    k_fc_mma<<<512, 512>>>(2, 1638400 + s * 32768, fcb, selout);
}

extern "C" void kernel_launch(void* const* d_in, const int* in_sizes, int n_in,
                              void* d_out, int out_size) {
    const float* p      = (const float*)d_in[0];
    const float* p2     = (const float*)d_in[1];
    const float* wp     = (const float*)d_in[2];
    const float* bp     = (const float*)d_in[3];
    const float* wp2    = (const float*)d_in[4];
    const float* bp2    = (const float*)d_in[5];
    const float* blk_w0 = (const float*)d_in[6];
    const float* blk_b0 = (const float*)d_in[7];
    const float* blk_w1 = (const float*)d_in[8];
    const float* blk_b1 = (const float*)d_in[9];
    const float* blk_ws = (const float*)d_in[10];
    const float* blkc_w0= (const float*)d_in[11];
    const float* blkc_b0= (const float*)d_in[12];
    const float* blkc_w1= (const float*)d_in[13];
    const float* blkc_b1= (const float*)d_in[14];
    const float* blkc_ws= (const float*)d_in[15];
    const float* fc_c_w = (const float*)d_in[16];
    const float* fc_c_b = (const float*)d_in[17];
    const float* fc_cc_w= (const float*)d_in[18];
    const float* fc_cc_b= (const float*)d_in[19];
    float* out = (float*)d_out;

    k_idx<<<256, 256>>>(p);
    k_layer0<<<65536, 256>>>(p, p2, wp, bp, wp2, bp2);

    prep_stream(blk_w0,  blk_w1,  blk_ws,  fc_c_w,  0);
    prep_stream(blkc_w0, blkc_w1, blkc_ws, fc_cc_w, 1);

    run_stream(0, 0, blk_b0,  blk_b1,  fc_c_b,  4);
    run_stream(1, 1, blkc_b0, blkc_b1, fc_cc_b, 5);

    // plane means: geo (with counts), then corr (reuses counts)
    k_clear_bins<<<49152, 256>>>();
    k_clear_cnt<<<1536, 256>>>();
    k_scatter_sum<<<65536, 128>>>(4, 1);
    k_transpose_div<<<dim3(512, 4, 24), dim3(32, 8)>>>(out, 0);
    k_clear_bins<<<49152, 256>>>();
    k_scatter_sum<<<65536, 128>>>(5, 0);
    k_transpose_div<<<dim3(512, 4, 24), dim3(32, 8)>>>(out, 3);
}

// round 9
// speedup vs baseline: 2.2489x; 1.0496x over previous
#include <cuda_runtime.h>
#include <cuda_bf16.h>
#include <cstdint>

// LocalPoolPointnetPPFusion: B=8, T=8192, H=128, C=128, R=128, NB=5
// mma.sync bf16 hi/lo (3-product) GEMMs with fused scatter-max / gather /
// plane-sum epilogues. Static smem only, no host API besides launches.
// (Resubmission of the unmeasured R8 design after an infra-side failure.)

// ------------------------- scratch ( __device__ globals ) -------------------
__device__ float    g_net256 [16777216];   // [65536,256] geo stream input
__device__ float    g_netc256[16777216];   // [65536,256] corr stream input
__device__ float    g_net    [ 8388608];   // [65536,128] current net
__device__ unsigned g_binsA  [50331648];   // 3 * 8 * 16384 * 128 (keys / f32 sums)
__device__ unsigned g_binsB  [50331648];
__device__ float    g_cnt    [  393216];   // 3 * 8 * 16384
__device__ int      g_idx    [  196608];   // 3 * 65536
__device__ __align__(16) __nv_bfloat16 g_wt[1703936];  // transposed h/l weights

__device__ __forceinline__ float* bufptr(int sel) {
    switch (sel) {
        case 0:  return g_net256;
        case 1:  return g_netc256;
        default: return g_net;
    }
}

__device__ __forceinline__ unsigned f2ord(float f) {
    unsigned u = __float_as_uint(f);
    return (u & 0x80000000u) ? ~u : (u | 0x80000000u);
}
__device__ __forceinline__ float ord2f(unsigned k) {
    return (k & 0x80000000u) ? __uint_as_float(k ^ 0x80000000u)
                             : __uint_as_float(~k);
}

__device__ __forceinline__ uint32_t smem_u32(const void* p) {
    uint32_t a;
    asm("{ .reg .u64 t; cvta.to.shared.u64 t, %1; cvt.u32.u64 %0, t; }"
        : "=r"(a) : "l"(p));
    return a;
}

#define LDSM4(r0, r1, r2, r3, addr)                                         \
    asm volatile("ldmatrix.sync.aligned.m8n8.x4.shared.b16 {%0,%1,%2,%3}, [%4];" \
                 : "=r"(r0), "=r"(r1), "=r"(r2), "=r"(r3) : "r"(addr))
#define LDSM2(r0, r1, addr)                                                 \
    asm volatile("ldmatrix.sync.aligned.m8n8.x2.shared.b16 {%0,%1}, [%2];"  \
                 : "=r"(r0), "=r"(r1) : "r"(addr))
#define MMA16816(c, a0, a1, a2, a3, b0, b1)                                 \
    asm volatile("mma.sync.aligned.m16n8k16.row.col.f32.bf16.bf16.f32 "     \
                 "{%0,%1,%2,%3}, {%4,%5,%6,%7}, {%8,%9}, {%0,%1,%2,%3};"    \
                 : "+f"((c)[0]), "+f"((c)[1]), "+f"((c)[2]), "+f"((c)[3])   \
                 : "r"(a0), "r"(a1), "r"(a2), "r"(a3), "r"(b0), "r"(b1))

__device__ __forceinline__ void split_hl(float v, __nv_bfloat16& h, __nv_bfloat16& l) {
    h = __float2bfloat16_rn(v);
    l = __float2bfloat16_rn(v - __bfloat162float(h));
}

// zero bf16 lanes of (h,l) where h's sign bit is set: exact relu h/l split.
__device__ __forceinline__ void relu_mask(uint32_t h, uint32_t l,
                                          uint32_t& rh, uint32_t& rl) {
    uint32_t t  = (h >> 15) & 0x00010001u;
    uint32_t zm = t * 0xFFFFu;
    rh = h & ~zm;
    rl = l & ~zm;
}

#define TST 40               // smem tile stride in bf16 elems (80B rows)

// ------------------------- init: idx + initial projections ------------------
__global__ void k_init(const float* __restrict__ p,  const float* __restrict__ p2,
                       const float* __restrict__ wp, const float* __restrict__ bp,
                       const float* __restrict__ wp2,const float* __restrict__ bp2) {
    int m = blockIdx.x, j = threadIdx.x;                 // 65536 x 256
    float a0 = p[3 * m], a1 = p[3 * m + 1], a2 = p[3 * m + 2];
    float q0 = p2[3 * m], q1 = p2[3 * m + 1], q2 = p2[3 * m + 2];
    float v  = fmaf(a0, wp[j],  fmaf(a1, wp[256 + j],  fmaf(a2, wp[512 + j],  bp[j])));
    float v2 = fmaf(q0, wp2[j], fmaf(q1, wp2[256 + j], fmaf(q2, wp2[512 + j], bp2[j])));
    g_net256 [(size_t)m * 256 + j] = v;
    g_netc256[(size_t)m * 256 + j] = v + v2;
    if (j == 0) {
        float nx = fminf(fmaxf(__fadd_rn(__fdiv_rn(a0, 1.001f), 0.5f), 0.0f), 0.999f);
        float ny = fminf(fmaxf(__fadd_rn(__fdiv_rn(a1, 1.001f), 0.5f), 0.0f), 0.999f);
        float nz = fminf(fmaxf(__fadd_rn(__fdiv_rn(a2, 1.001f), 0.5f), 0.0f), 0.999f);
        int gx = (int)floorf(__fmul_rn(nx, 128.0f));
        int gy = (int)floorf(__fmul_rn(ny, 128.0f));
        int gz = (int)floorf(__fmul_rn(nz, 128.0f));
        g_idx[m]          = gx + 128 * gz;
        g_idx[65536 + m]  = gx + 128 * gy;
        g_idx[131072 + m] = gy + 128 * gz;
    }
}

// ------------------------- weight prep: transpose + h/l split ---------------
__global__ void k_prep(const float* __restrict__ w, int K, int ooff) {
    int k = blockIdx.x * 128 + threadIdx.x;
    int n = blockIdx.y;
    float v = w[(size_t)k * 128 + n];
    __nv_bfloat16 h, l;
    split_hl(v, h, l);
    g_wt[ooff + (size_t)n * K + k] = h;
    g_wt[ooff + 128 * K + (size_t)n * K + k] = l;
}

// ------------------------- clears -------------------------------------------
__global__ void k_clear_bins(int sel) {
    size_t i = (size_t)blockIdx.x * 256 + threadIdx.x;
    ((uint4*)(sel ? g_binsB : g_binsA))[i] = make_uint4(0u, 0u, 0u, 0u);
}
__global__ void k_clear_cnt() {
    int i = blockIdx.x * 256 + threadIdx.x;
    g_cnt[i] = 0.0f;
}

// ------------------------- fused ResNet block (mma.sync) --------------------
// out = x@ws + relu( relu(x)@w0 + b0 )@w1 + b1,  x = [A 128 | pooled/B 128].
// gatherSel >= 0: cols 128..255 of x come from summing 3 plane bins (fused
// _pool_local gather). scatterSel >= 0: epilogue atomicMax-scatters the
// output into the selected bins buffer (fused scatter-max for next pooling).
__global__ void __launch_bounds__(512)
k_resblock_mma(int selA, int ldA, int offA, int selB, int ldB, int offB,
               int gatherSel, int scatterSel,
               int woff, const float* __restrict__ b0, const float* __restrict__ b1)
{
    __shared__ __nv_bfloat16 sXh[128 * TST], sXl[128 * TST];
    __shared__ __nv_bfloat16 sWh[128 * TST], sWl[128 * TST];
    const uint32_t aXh = smem_u32(sXh), aXl = smem_u32(sXl);
    const uint32_t aWh = smem_u32(sWh), aWl = smem_u32(sWl);

    const int tid = threadIdx.x, wid = tid >> 5, lane = tid & 31;
    const int wm = (wid >> 1) * 16;            // warp row base (0..112)
    const int wn = (wid & 1) * 64;             // warp col base (0 or 64)
    const size_t m0 = (size_t)blockIdx.x * 128;

    const float* xA = bufptr(selA) + offA;
    const float* xB = bufptr(selB) + offB;
    const unsigned* binsIn = (gatherSel == 1) ? g_binsB : g_binsA;
    const __nv_bfloat16* w0h = g_wt + woff;          // [128][256]
    const __nv_bfloat16* w0l = w0h + 32768;
    const __nv_bfloat16* wsh = w0h + 65536;
    const __nv_bfloat16* wsl = w0h + 98304;
    const __nv_bfloat16* w1h = w0h + 131072;         // [128][128]
    const __nv_bfloat16* w1l = w0h + 147456;

    float accN[32], accS[32];
#pragma unroll
    for (int i = 0; i < 32; i++) { accN[i] = 0.0f; accS[i] = 0.0f; }

    const uint32_t akOff = (uint32_t)((wm + (lane & 15)) * TST + ((lane >> 4) & 1) * 8) * 2;
    const uint32_t bkOff = (uint32_t)((wn + (lane & 7)) * TST + ((lane >> 3) & 1) * 8) * 2;
    const int wn_ = tid >> 2, wq_ = tid & 3;   // weight-chunk copy indices

    // ---------------- stage A: K = 256, 8 chunks of 32 ----------------------
    for (int kc = 0; kc < 256; kc += 32) {
        __syncthreads();
        if (kc < 128 || gatherSel < 0) {
            const float* xS = (kc < 128) ? xA : xB;
            const int ldS   = (kc < 128) ? ldA : ldB;
            const int cb    = kc & 127;
#pragma unroll
            for (int it = 0; it < 4; it++) {
                int e = it * 512 + tid;
                int r = e >> 4, cp = e & 15;
                float2 v = *(const float2*)&xS[(m0 + r) * ldS + cb + cp * 2];
                __nv_bfloat162 h2, l2;
                split_hl(v.x, h2.x, l2.x);
                split_hl(v.y, h2.y, l2.y);
                int o = r * TST + cp * 2;
                *(__nv_bfloat162*)&sXh[o] = h2;
                *(__nv_bfloat162*)&sXl[o] = l2;
            }
        } else {
            // fused gather: pooled[:, cb..cb+32) = sum over 3 planes of bins
            const int cb = kc - 128;
#pragma unroll
            for (int it = 0; it < 4; it++) {
                int e = it * 512 + tid;
                int r = e >> 4, cp = e & 15;
                int m = (int)m0 + r;
                int b = m >> 13;
                float sx = 0.0f, sy = 0.0f;
#pragma unroll
                for (int p = 0; p < 3; p++) {
                    int bin = g_idx[p * 65536 + m];
                    uint2 kk = *(const uint2*)&binsIn[
                        ((size_t)p * 131072 + b * 16384 + bin) * 128 + cb + cp * 2];
                    if (kk.x) sx += ord2f(kk.x);
                    if (kk.y) sy += ord2f(kk.y);
                }
                __nv_bfloat162 h2, l2;
                split_hl(sx, h2.x, l2.x);
                split_hl(sy, h2.y, l2.y);
                int o = r * TST + cp * 2;
                *(__nv_bfloat162*)&sXh[o] = h2;
                *(__nv_bfloat162*)&sXl[o] = l2;
            }
        }
        *(uint4*)&sWh[wn_ * TST + wq_ * 8] = *(const uint4*)&w0h[(size_t)wn_ * 256 + kc + wq_ * 8];
        *(uint4*)&sWl[wn_ * TST + wq_ * 8] = *(const uint4*)&w0l[(size_t)wn_ * 256 + kc + wq_ * 8];
        __syncthreads();

        uint32_t fxh[2][4], fxl[2][4];
#pragma unroll
        for (int ks = 0; ks < 2; ks++) {       // accN pass: relu(x) @ w0
            LDSM4(fxh[ks][0], fxh[ks][1], fxh[ks][2], fxh[ks][3], aXh + akOff + ks * 32);
            LDSM4(fxl[ks][0], fxl[ks][1], fxl[ks][2], fxl[ks][3], aXl + akOff + ks * 32);
            uint32_t frh[4], frl[4];
#pragma unroll
            for (int i = 0; i < 4; i++) relu_mask(fxh[ks][i], fxl[ks][i], frh[i], frl[i]);
#pragma unroll
            for (int jn = 0; jn < 8; jn++) {
                uint32_t ba = bkOff + ks * 32 + jn * (8 * TST * 2);
                uint32_t p0, p1, q0, q1;
                LDSM2(p0, p1, aWh + ba);
                LDSM2(q0, q1, aWl + ba);
                MMA16816(accN + jn * 4, frh[0], frh[1], frh[2], frh[3], p0, p1);
                MMA16816(accN + jn * 4, frh[0], frh[1], frh[2], frh[3], q0, q1);
                MMA16816(accN + jn * 4, frl[0], frl[1], frl[2], frl[3], p0, p1);
            }
        }
        __syncthreads();
        *(uint4*)&sWh[wn_ * TST + wq_ * 8] = *(const uint4*)&wsh[(size_t)wn_ * 256 + kc + wq_ * 8];
        *(uint4*)&sWl[wn_ * TST + wq_ * 8] = *(const uint4*)&wsl[(size_t)wn_ * 256 + kc + wq_ * 8];
        __syncthreads();
#pragma unroll
        for (int ks = 0; ks < 2; ks++) {       // accS pass: x @ ws
#pragma unroll
            for (int jn = 0; jn < 8; jn++) {
                uint32_t ba = bkOff + ks * 32 + jn * (8 * TST * 2);
                uint32_t p0, p1, q0, q1;
                LDSM2(p0, p1, aWh + ba);
                LDSM2(q0, q1, aWl + ba);
                MMA16816(accS + jn * 4, fxh[ks][0], fxh[ks][1], fxh[ks][2], fxh[ks][3], p0, p1);
                MMA16816(accS + jn * 4, fxh[ks][0], fxh[ks][1], fxh[ks][2], fxh[ks][3], q0, q1);
                MMA16816(accS + jn * 4, fxl[ks][0], fxl[ks][1], fxl[ks][2], fxl[ks][3], p0, p1);
            }
        }
    }

    // ---------------- stage B: K = 128, 4 chunks of 32 ----------------------
    for (int kb = 0; kb < 4; kb++) {
        __syncthreads();
        if (wn == (kb >> 1) * 64) {
            int row0 = wm + (lane >> 2);
#pragma unroll
            for (int jj = 0; jj < 4; jj++) {
                int jn = (kb & 1) * 4 + jj;
                int c  = wn + (lane & 3) * 2 + jn * 8;
                int lc = jj * 8 + (lane & 3) * 2;
                float bv0 = b0[c], bv1 = b0[c + 1];
                float v00 = fmaxf(accN[jn * 4 + 0] + bv0, 0.0f);
                float v01 = fmaxf(accN[jn * 4 + 1] + bv1, 0.0f);
                float v10 = fmaxf(accN[jn * 4 + 2] + bv0, 0.0f);
                float v11 = fmaxf(accN[jn * 4 + 3] + bv1, 0.0f);
                __nv_bfloat162 h2, l2;
                split_hl(v00, h2.x, l2.x); split_hl(v01, h2.y, l2.y);
                *(__nv_bfloat162*)&sXh[row0 * TST + lc] = h2;
                *(__nv_bfloat162*)&sXl[row0 * TST + lc] = l2;
                split_hl(v10, h2.x, l2.x); split_hl(v11, h2.y, l2.y);
                *(__nv_bfloat162*)&sXh[(row0 + 8) * TST + lc] = h2;
                *(__nv_bfloat162*)&sXl[(row0 + 8) * TST + lc] = l2;
            }
        }
        *(uint4*)&sWh[wn_ * TST + wq_ * 8] = *(const uint4*)&w1h[(size_t)wn_ * 128 + kb * 32 + wq_ * 8];
        *(uint4*)&sWl[wn_ * TST + wq_ * 8] = *(const uint4*)&w1l[(size_t)wn_ * 128 + kb * 32 + wq_ * 8];
        __syncthreads();
#pragma unroll
        for (int ks = 0; ks < 2; ks++) {
            uint32_t fh[4], fl[4];
            LDSM4(fh[0], fh[1], fh[2], fh[3], aXh + akOff + ks * 32);
            LDSM4(fl[0], fl[1], fl[2], fl[3], aXl + akOff + ks * 32);
#pragma unroll
            for (int jn = 0; jn < 8; jn++) {
                uint32_t ba = bkOff + ks * 32 + jn * (8 * TST * 2);
                uint32_t p0, p1, q0, q1;
                LDSM2(p0, p1, aWh + ba);
                LDSM2(q0, q1, aWl + ba);
                MMA16816(accS + jn * 4, fh[0], fh[1], fh[2], fh[3], p0, p1);
                MMA16816(accS + jn * 4, fh[0], fh[1], fh[2], fh[3], q0, q1);
                MMA16816(accS + jn * 4, fl[0], fl[1], fl[2], fl[3], p0, p1);
            }
        }
    }

    // -------- epilogue: g_net = accS + b1 (+ fused scatter-max) -------------
    {
        int row0 = wm + (lane >> 2);
        int cb2 = wn + (lane & 3) * 2;
        size_t mA = m0 + row0, mB = mA + 8;
        unsigned* bo = (scatterSel == 1) ? g_binsB : g_binsA;
        size_t baseA[3], baseB[3];
        if (scatterSel >= 0) {
            int bA = (int)(mA >> 13), bB = (int)(mB >> 13);
#pragma unroll
            for (int p = 0; p < 3; p++) {
                baseA[p] = ((size_t)p * 131072 + bA * 16384 + g_idx[p * 65536 + (int)mA]) * 128;
                baseB[p] = ((size_t)p * 131072 + bB * 16384 + g_idx[p * 65536 + (int)mB]) * 128;
            }
        }
#pragma unroll
        for (int jn = 0; jn < 8; jn++) {
            int c = cb2 + jn * 8;
            float bv0 = b1[c], bv1 = b1[c + 1];
            float2 v0 = make_float2(accS[jn * 4 + 0] + bv0, accS[jn * 4 + 1] + bv1);
            float2 v1 = make_float2(accS[jn * 4 + 2] + bv0, accS[jn * 4 + 3] + bv1);
            *(float2*)&g_net[mA * 128 + c] = v0;
            *(float2*)&g_net[mB * 128 + c] = v1;
            if (scatterSel >= 0) {
                unsigned k0x = f2ord(v0.x), k0y = f2ord(v0.y);
                unsigned k1x = f2ord(v1.x), k1y = f2ord(v1.y);
#pragma unroll
                for (int p = 0; p < 3; p++) {
                    atomicMax(&bo[baseA[p] + c], k0x);
                    atomicMax(&bo[baseA[p] + c + 1], k0y);
                    atomicMax(&bo[baseB[p] + c], k1x);
                    atomicMax(&bo[baseB[p] + c + 1], k1y);
                }
            }
        }
    }
}

// ------------------------- final fc (mma.sync) + fused plane scatter --------
__global__ void __launch_bounds__(512)
k_fc_mma(int selx, int woff, const float* __restrict__ b, int scatterSel, int doCount)
{
    __shared__ __nv_bfloat16 sXh[128 * TST], sXl[128 * TST];
    __shared__ __nv_bfloat16 sWh[128 * TST], sWl[128 * TST];
    const uint32_t aXh = smem_u32(sXh), aXl = smem_u32(sXl);
    const uint32_t aWh = smem_u32(sWh), aWl = smem_u32(sWl);

    const int tid = threadIdx.x, wid = tid >> 5, lane = tid & 31;
    const int wm = (wid >> 1) * 16;
    const int wn = (wid & 1) * 64;
    const size_t m0 = (size_t)blockIdx.x * 128;

    const float* x = bufptr(selx);
    const __nv_bfloat16* wh = g_wt + woff;   // [128][128]
    const __nv_bfloat16* wl = wh + 16384;

    float acc[32];
#pragma unroll
    for (int i = 0; i < 32; i++) acc[i] = 0.0f;

    const uint32_t akOff = (uint32_t)((wm + (lane & 15)) * TST + ((lane >> 4) & 1) * 8) * 2;
    const uint32_t bkOff = (uint32_t)((wn + (lane & 7)) * TST + ((lane >> 3) & 1) * 8) * 2;
    const int wn_ = tid >> 2, wq_ = tid & 3;

    for (int kc = 0; kc < 128; kc += 32) {
        __syncthreads();
#pragma unroll
        for (int it = 0; it < 4; it++) {
            int e = it * 512 + tid;
            int r = e >> 4, cp = e & 15;
            float2 v = *(const float2*)&x[(m0 + r) * 128 + kc + cp * 2];
            __nv_bfloat162 h2, l2;
            split_hl(v.x, h2.x, l2.x);
            split_hl(v.y, h2.y, l2.y);
            int o = r * TST + cp * 2;
            *(__nv_bfloat162*)&sXh[o] = h2;
            *(__nv_bfloat162*)&sXl[o] = l2;
        }
        *(uint4*)&sWh[wn_ * TST + wq_ * 8] = *(const uint4*)&wh[(size_t)wn_ * 128 + kc + wq_ * 8];
        *(uint4*)&sWl[wn_ * TST + wq_ * 8] = *(const uint4*)&wl[(size_t)wn_ * 128 + kc + wq_ * 8];
        __syncthreads();
#pragma unroll
        for (int ks = 0; ks < 2; ks++) {
            uint32_t fh[4], fl[4];
            LDSM4(fh[0], fh[1], fh[2], fh[3], aXh + akOff + ks * 32);
            LDSM4(fl[0], fl[1], fl[2], fl[3], aXl + akOff + ks * 32);
#pragma unroll
            for (int jn = 0; jn < 8; jn++) {
                uint32_t ba = bkOff + ks * 32 + jn * (8 * TST * 2);
                uint32_t p0, p1, q0, q1;
                LDSM2(p0, p1, aWh + ba);
                LDSM2(q0, q1, aWl + ba);
                MMA16816(acc + jn * 4, fh[0], fh[1], fh[2], fh[3], p0, p1);
                MMA16816(acc + jn * 4, fh[0], fh[1], fh[2], fh[3], q0, q1);
                MMA16816(acc + jn * 4, fl[0], fl[1], fl[2], fl[3], p0, p1);
            }
        }
    }

    // epilogue: scatter-add c values into plane-sum bins (+ counts once)
    {
        float* so = (float*)((scatterSel == 1) ? g_binsB : g_binsA);
        int row0 = wm + (lane >> 2);
        int cb2 = wn + (lane & 3) * 2;
        size_t mA = m0 + row0, mB = mA + 8;
        int bA = (int)(mA >> 13), bB = (int)(mB >> 13);
        int binA[3], binB[3];
        size_t baseA[3], baseB[3];
#pragma unroll
        for (int p = 0; p < 3; p++) {
            binA[p] = g_idx[p * 65536 + (int)mA];
            binB[p] = g_idx[p * 65536 + (int)mB];
            baseA[p] = ((size_t)p * 131072 + bA * 16384 + binA[p]) * 128;
            baseB[p] = ((size_t)p * 131072 + bB * 16384 + binB[p]) * 128;
        }
#pragma unroll
        for (int jn = 0; jn < 8; jn++) {
            int c = cb2 + jn * 8;
            float bv0 = b[c], bv1 = b[c + 1];
            float v0x = acc[jn * 4 + 0] + bv0, v0y = acc[jn * 4 + 1] + bv1;
            float v1x = acc[jn * 4 + 2] + bv0, v1y = acc[jn * 4 + 3] + bv1;
#pragma unroll
            for (int p = 0; p < 3; p++) {
                atomicAdd(&so[baseA[p] + c], v0x);
                atomicAdd(&so[baseA[p] + c + 1], v0y);
                atomicAdd(&so[baseB[p] + c], v1x);
                atomicAdd(&so[baseB[p] + c + 1], v1y);
            }
        }
        if (doCount && wn == 0 && (lane & 3) == 0) {
#pragma unroll
            for (int p = 0; p < 3; p++) {
                atomicAdd(&g_cnt[p * 131072 + bA * 16384 + binA[p]], 1.0f);
                atomicAdd(&g_cnt[p * 131072 + bB * 16384 + binB[p]], 1.0f);
            }
        }
    }
}

// ------------------------- plane mean writeback -----------------------------
__global__ void k_transpose_div(float* __restrict__ outb, int po, int binsSel) {
    __shared__ float t[32][33];
    int p = blockIdx.z >> 3, b = blockIdx.z & 7;
    int bin0 = blockIdx.x * 32, c0 = blockIdx.y * 32;
    const float* sums = (const float*)(binsSel ? g_binsB : g_binsA);
    size_t base = (size_t)p * 131072 + (size_t)b * 16384;
#pragma unroll
    for (int i = 0; i < 4; i++)
        t[threadIdx.y + 8 * i][threadIdx.x] =
            sums[(base + bin0 + threadIdx.y + 8 * i) * 128 + c0 + threadIdx.x];
    __syncthreads();
    float cv = fmaxf(g_cnt[base + bin0 + threadIdx.x], 1.0f);
#pragma unroll
    for (int i = 0; i < 4; i++) {
        int c = c0 + threadIdx.y + 8 * i;
        outb[(((size_t)(p + po) * 8 + b) * 128 + c) * 16384 + bin0 + threadIdx.x] =
            t[threadIdx.x][threadIdx.y + 8 * i] / cv;
    }
}

// ------------------------- driver -------------------------------------------
static inline int wt_off_blk(int s, int i) { return (s * 5 + i) * 163840; }

static void prep_block(const float* w0, const float* w1, const float* ws,
                       int s, int i) {
    int off = wt_off_blk(s, i);
    k_prep<<<dim3(2, 128), 128>>>(w0 + (size_t)i * 32768, 256, off);
    k_prep<<<dim3(2, 128), 128>>>(ws + (size_t)i * 32768, 256, off + 65536);
    k_prep<<<dim3(1, 128), 128>>>(w1 + (size_t)i * 16384, 128, off + 131072);
}

extern "C" void kernel_launch(void* const* d_in, const int* in_sizes, int n_in,
                              void* d_out, int out_size) {
    const float* p      = (const float*)d_in[0];
    const float* p2     = (const float*)d_in[1];
    const float* wp     = (const float*)d_in[2];
    const float* bp     = (const float*)d_in[3];
    const float* wp2    = (const float*)d_in[4];
    const float* bp2    = (const float*)d_in[5];
    const float* blk_w0 = (const float*)d_in[6];
    const float* blk_b0 = (const float*)d_in[7];
    const float* blk_w1 = (const float*)d_in[8];
    const float* blk_b1 = (const float*)d_in[9];
    const float* blk_ws = (const float*)d_in[10];
    const float* blkc_w0= (const float*)d_in[11];
    const float* blkc_b0= (const float*)d_in[12];
    const float* blkc_w1= (const float*)d_in[13];
    const float* blkc_b1= (const float*)d_in[14];
    const float* blkc_ws= (const float*)d_in[15];
    const float* fc_c_w = (const float*)d_in[16];
    const float* fc_c_b = (const float*)d_in[17];
    const float* fc_cc_w= (const float*)d_in[18];
    const float* fc_cc_b= (const float*)d_in[19];
    float* out = (float*)d_out;

    // launches 1-5: clearA, init, prep(s0,i0) x3 -> launch 6 is k_resblock_mma
    k_clear_bins<<<49152, 256>>>(0);
    k_init<<<65536, 256>>>(p, p2, wp, bp, wp2, bp2);
    prep_block(blk_w0, blk_w1, blk_ws, 0, 0);

    // launch 6 (ncu -s 5 -c 1 captures this): first resblock, scatter -> A
    k_resblock_mma<<<512, 512>>>(0, 256, 0, 0, 256, 128, -1, 0,
                                 wt_off_blk(0, 0), blk_b0, blk_b1);

    // remaining weight preps
    for (int i = 1; i < 5; i++) prep_block(blk_w0, blk_w1, blk_ws, 0, i);
    for (int i = 0; i < 5; i++) prep_block(blkc_w0, blkc_w1, blkc_ws, 1, i);
    k_prep<<<dim3(1, 128), 128>>>(fc_c_w,  128, 1638400);
    k_prep<<<dim3(1, 128), 128>>>(fc_cc_w, 128, 1671168);

    // stream 0: alternate bins A(0)/B(1)
    k_clear_bins<<<49152, 256>>>(1);
    k_resblock_mma<<<512, 512>>>(2, 128, 0, 2, 128, 0, 0, 1,
                                 wt_off_blk(0, 1), blk_b0 + 128, blk_b1 + 128);
    k_clear_bins<<<49152, 256>>>(0);
    k_resblock_mma<<<512, 512>>>(2, 128, 0, 2, 128, 0, 1, 0,
                                 wt_off_blk(0, 2), blk_b0 + 256, blk_b1 + 256);
    k_clear_bins<<<49152, 256>>>(1);
    k_resblock_mma<<<512, 512>>>(2, 128, 0, 2, 128, 0, 0, 1,
                                 wt_off_blk(0, 3), blk_b0 + 384, blk_b1 + 384);
    k_resblock_mma<<<512, 512>>>(2, 128, 0, 2, 128, 0, 1, -1,
                                 wt_off_blk(0, 4), blk_b0 + 512, blk_b1 + 512);
    k_clear_bins<<<49152, 256>>>(0);
    k_clear_cnt<<<1536, 256>>>();
    k_fc_mma<<<512, 512>>>(2, 1638400, fc_c_b, 0, 1);
    k_transpose_div<<<dim3(512, 4, 24), dim3(32, 8)>>>(out, 0, 0);

    // stream 1
    k_clear_bins<<<49152, 256>>>(1);
    k_resblock_mma<<<512, 512>>>(1, 256, 0, 1, 256, 128, -1, 1,
                                 wt_off_blk(1, 0), blkc_b0, blkc_b1);
    k_clear_bins<<<49152, 256>>>(0);
    k_resblock_mma<<<512, 512>>>(2, 128, 0, 2, 128, 0, 1, 0,
                                 wt_off_blk(1, 1), blkc_b0 + 128, blkc_b1 + 128);
    k_clear_bins<<<49152, 256>>>(1);
    k_resblock_mma<<<512, 512>>>(2, 128, 0, 2, 128, 0, 0, 1,
                                 wt_off_blk(1, 2), blkc_b0 + 256, blkc_b1 + 256);
    k_clear_bins<<<49152, 256>>>(0);
    k_resblock_mma<<<512, 512>>>(2, 128, 0, 2, 128, 0, 1, 0,
                                 wt_off_blk(1, 3), blkc_b0 + 384, blkc_b1 + 384);
    k_resblock_mma<<<512, 512>>>(2, 128, 0, 2, 128, 0, 0, -1,
                                 wt_off_blk(1, 4), blkc_b0 + 512, blkc_b1 + 512);
    k_clear_bins<<<49152, 256>>>(1);
    k_fc_mma<<<512, 512>>>(2, 1671168, fc_cc_b, 1, 0);
    k_transpose_div<<<dim3(512, 4, 24), dim3(32, 8)>>>(out, 3, 1);
}

// round 12
// speedup vs baseline: 2.2897x; 1.0181x over previous
#include <cuda_runtime.h>
#include <cuda_bf16.h>
#include <cstdint>

// LocalPoolPointnetPPFusion: B=8, T=8192, H=128, C=128, R=128, NB=5
// mma.sync bf16 hi/lo (3-product) GEMMs with fused scatter-max / gather /
// plane-sum epilogues. R9-proven 512-thread kernels + single-launch weight
// prep (bisecting the R10 delta: the 256-thread CTA change is withheld).

// ------------------------- scratch ( __device__ globals ) -------------------
__device__ float    g_net256 [16777216];   // [65536,256] geo stream input
__device__ float    g_netc256[16777216];   // [65536,256] corr stream input
__device__ float    g_net    [ 8388608];   // [65536,128] current net
__device__ unsigned g_binsA  [50331648];   // 3 * 8 * 16384 * 128 (keys / f32 sums)
__device__ unsigned g_binsB  [50331648];
__device__ float    g_cnt    [  393216];   // 3 * 8 * 16384
__device__ int      g_idx    [  196608];   // 3 * 65536
__device__ __align__(16) __nv_bfloat16 g_wt[1703936];  // transposed h/l weights

__device__ __forceinline__ float* bufptr(int sel) {
    switch (sel) {
        case 0:  return g_net256;
        case 1:  return g_netc256;
        default: return g_net;
    }
}

__device__ __forceinline__ unsigned f2ord(float f) {
    unsigned u = __float_as_uint(f);
    return (u & 0x80000000u) ? ~u : (u | 0x80000000u);
}
__device__ __forceinline__ float ord2f(unsigned k) {
    return (k & 0x80000000u) ? __uint_as_float(k ^ 0x80000000u)
                             : __uint_as_float(~k);
}

__device__ __forceinline__ uint32_t smem_u32(const void* p) {
    uint32_t a;
    asm("{ .reg .u64 t; cvta.to.shared.u64 t, %1; cvt.u32.u64 %0, t; }"
        : "=r"(a) : "l"(p));
    return a;
}

#define LDSM4(r0, r1, r2, r3, addr)                                         \
    asm volatile("ldmatrix.sync.aligned.m8n8.x4.shared.b16 {%0,%1,%2,%3}, [%4];" \
                 : "=r"(r0), "=r"(r1), "=r"(r2), "=r"(r3) : "r"(addr))
#define LDSM2(r0, r1, addr)                                                 \
    asm volatile("ldmatrix.sync.aligned.m8n8.x2.shared.b16 {%0,%1}, [%2];"  \
                 : "=r"(r0), "=r"(r1) : "r"(addr))
#define MMA16816(c, a0, a1, a2, a3, b0, b1)                                 \
    asm volatile("mma.sync.aligned.m16n8k16.row.col.f32.bf16.bf16.f32 "     \
                 "{%0,%1,%2,%3}, {%4,%5,%6,%7}, {%8,%9}, {%0,%1,%2,%3};"    \
                 : "+f"((c)[0]), "+f"((c)[1]), "+f"((c)[2]), "+f"((c)[3])   \
                 : "r"(a0), "r"(a1), "r"(a2), "r"(a3), "r"(b0), "r"(b1))

__device__ __forceinline__ void split_hl(float v, __nv_bfloat16& h, __nv_bfloat16& l) {
    h = __float2bfloat16_rn(v);
    l = __float2bfloat16_rn(v - __bfloat162float(h));
}

// zero bf16 lanes of (h,l) where h's sign bit is set: exact relu h/l split.
__device__ __forceinline__ void relu_mask(uint32_t h, uint32_t l,
                                          uint32_t& rh, uint32_t& rl) {
    uint32_t t  = (h >> 15) & 0x00010001u;
    uint32_t zm = t * 0xFFFFu;
    rh = h & ~zm;
    rl = l & ~zm;
}

#define TST 40               // smem tile stride in bf16 elems (80B rows)

// ------------------------- init: idx + initial projections ------------------
__global__ void k_init(const float* __restrict__ p,  const float* __restrict__ p2,
                       const float* __restrict__ wp, const float* __restrict__ bp,
                       const float* __restrict__ wp2,const float* __restrict__ bp2) {
    int m = blockIdx.x, j = threadIdx.x;                 // 65536 x 256
    float a0 = p[3 * m], a1 = p[3 * m + 1], a2 = p[3 * m + 2];
    float q0 = p2[3 * m], q1 = p2[3 * m + 1], q2 = p2[3 * m + 2];
    float v  = fmaf(a0, wp[j],  fmaf(a1, wp[256 + j],  fmaf(a2, wp[512 + j],  bp[j])));
    float v2 = fmaf(q0, wp2[j], fmaf(q1, wp2[256 + j], fmaf(q2, wp2[512 + j], bp2[j])));
    g_net256 [(size_t)m * 256 + j] = v;
    g_netc256[(size_t)m * 256 + j] = v + v2;
    if (j == 0) {
        float nx = fminf(fmaxf(__fadd_rn(__fdiv_rn(a0, 1.001f), 0.5f), 0.0f), 0.999f);
        float ny = fminf(fmaxf(__fadd_rn(__fdiv_rn(a1, 1.001f), 0.5f), 0.0f), 0.999f);
        float nz = fminf(fmaxf(__fadd_rn(__fdiv_rn(a2, 1.001f), 0.5f), 0.0f), 0.999f);
        int gx = (int)floorf(__fmul_rn(nx, 128.0f));
        int gy = (int)floorf(__fmul_rn(ny, 128.0f));
        int gz = (int)floorf(__fmul_rn(nz, 128.0f));
        g_idx[m]          = gx + 128 * gz;
        g_idx[65536 + m]  = gx + 128 * gy;
        g_idx[131072 + m] = gy + 128 * gz;
    }
}

// ------------------------- weight prep: ONE launch for all weights ----------
// Layout per stream s, block i at (s*5+i)*163840:
//   w0T h/l (2*32768) | wsT h/l (2*32768) | w1T h/l (2*16384)
// fc weights at 1638400 + s*32768.
__global__ void k_prep_all(const float* __restrict__ w0a, const float* __restrict__ w1a,
                           const float* __restrict__ wsa, const float* __restrict__ w0c,
                           const float* __restrict__ w1c, const float* __restrict__ wsc,
                           const float* __restrict__ fca, const float* __restrict__ fcc) {
    int idx = blockIdx.x * 256 + threadIdx.x;            // 3328 blocks -> 851968
    int s = idx / 425984;
    int r = idx - s * 425984;
    const float* w;
    int K, ooff, e;
    if (r < 409600) {
        int i = r / 81920;
        int j = r - i * 81920;
        int off = (s * 5 + i) * 163840;
        if (j < 32768)      { w = (s ? w0c : w0a) + (size_t)i * 32768; K = 256; ooff = off;          e = j; }
        else if (j < 65536) { w = (s ? wsc : wsa) + (size_t)i * 32768; K = 256; ooff = off + 65536;  e = j - 32768; }
        else                { w = (s ? w1c : w1a) + (size_t)i * 16384; K = 128; ooff = off + 131072; e = j - 65536; }
    } else {
        w = s ? fcc : fca; K = 128; ooff = 1638400 + s * 32768; e = r - 409600;
    }
    int n = e / K, k = e - n * K;
    float v = w[(size_t)k * 128 + n];
    __nv_bfloat16 h, l;
    split_hl(v, h, l);
    g_wt[ooff + (size_t)n * K + k] = h;
    g_wt[ooff + 128 * K + (size_t)n * K + k] = l;
}

// ------------------------- clears -------------------------------------------
__global__ void k_clear_bins(int sel) {
    size_t i = (size_t)blockIdx.x * 256 + threadIdx.x;
    ((uint4*)(sel ? g_binsB : g_binsA))[i] = make_uint4(0u, 0u, 0u, 0u);
}
__global__ void k_clear_cnt() {
    int i = blockIdx.x * 256 + threadIdx.x;
    g_cnt[i] = 0.0f;
}

// ------------------------- fused ResNet block (mma.sync) --------------------
// out = x@ws + relu( relu(x)@w0 + b0 )@w1 + b1,  x = [A 128 | pooled/B 128].
// CTA: 512 threads = 16 warps; M-tile 128 (8 row-warps x 2 col-warps).
__global__ void __launch_bounds__(512)
k_resblock_mma(int selA, int ldA, int offA, int selB, int ldB, int offB,
               int gatherSel, int scatterSel,
               int woff, const float* __restrict__ b0, const float* __restrict__ b1)
{
    __shared__ __nv_bfloat16 sXh[128 * TST], sXl[128 * TST];
    __shared__ __nv_bfloat16 sWh[128 * TST], sWl[128 * TST];
    const uint32_t aXh = smem_u32(sXh), aXl = smem_u32(sXl);
    const uint32_t aWh = smem_u32(sWh), aWl = smem_u32(sWl);

    const int tid = threadIdx.x, wid = tid >> 5, lane = tid & 31;
    const int wm = (wid >> 1) * 16;            // warp row base (0..112)
    const int wn = (wid & 1) * 64;             // warp col base (0 or 64)
    const size_t m0 = (size_t)blockIdx.x * 128;

    const float* xA = bufptr(selA) + offA;
    const float* xB = bufptr(selB) + offB;
    const unsigned* binsIn = (gatherSel == 1) ? g_binsB : g_binsA;
    const __nv_bfloat16* w0h = g_wt + woff;          // [128][256]
    const __nv_bfloat16* w0l = w0h + 32768;
    const __nv_bfloat16* wsh = w0h + 65536;
    const __nv_bfloat16* wsl = w0h + 98304;
    const __nv_bfloat16* w1h = w0h + 131072;         // [128][128]
    const __nv_bfloat16* w1l = w0h + 147456;

    float accN[32], accS[32];
#pragma unroll
    for (int i = 0; i < 32; i++) { accN[i] = 0.0f; accS[i] = 0.0f; }

    const uint32_t akOff = (uint32_t)((wm + (lane & 15)) * TST + ((lane >> 4) & 1) * 8) * 2;
    const uint32_t bkOff = (uint32_t)((wn + (lane & 7)) * TST + ((lane >> 3) & 1) * 8) * 2;
    const int wn_ = tid >> 2, wq_ = tid & 3;   // weight-chunk copy indices

    // ---------------- stage A: K = 256, 8 chunks of 32 ----------------------
    for (int kc = 0; kc < 256; kc += 32) {
        __syncthreads();
        if (kc < 128 || gatherSel < 0) {
            const float* xS = (kc < 128) ? xA : xB;
            const int ldS   = (kc < 128) ? ldA : ldB;
            const int cb    = kc & 127;
#pragma unroll
            for (int it = 0; it < 4; it++) {
                int e = it * 512 + tid;
                int r = e >> 4, cp = e & 15;
                float2 v = *(const float2*)&xS[(m0 + r) * ldS + cb + cp * 2];
                __nv_bfloat162 h2, l2;
                split_hl(v.x, h2.x, l2.x);
                split_hl(v.y, h2.y, l2.y);
                int o = r * TST + cp * 2;
                *(__nv_bfloat162*)&sXh[o] = h2;
                *(__nv_bfloat162*)&sXl[o] = l2;
            }
        } else {
            // fused gather: pooled[:, cb..cb+32) = sum over 3 planes of bins
            const int cb = kc - 128;
#pragma unroll
            for (int it = 0; it < 4; it++) {
                int e = it * 512 + tid;
                int r = e >> 4, cp = e & 15;
                int m = (int)m0 + r;
                int b = m >> 13;
                float sx = 0.0f, sy = 0.0f;
#pragma unroll
                for (int p = 0; p < 3; p++) {
                    int bin = g_idx[p * 65536 + m];
                    uint2 kk = *(const uint2*)&binsIn[
                        ((size_t)p * 131072 + b * 16384 + bin) * 128 + cb + cp * 2];
                    if (kk.x) sx += ord2f(kk.x);
                    if (kk.y) sy += ord2f(kk.y);
                }
                __nv_bfloat162 h2, l2;
                split_hl(sx, h2.x, l2.x);
                split_hl(sy, h2.y, l2.y);
                int o = r * TST + cp * 2;
                *(__nv_bfloat162*)&sXh[o] = h2;
                *(__nv_bfloat162*)&sXl[o] = l2;
            }
        }
        *(uint4*)&sWh[wn_ * TST + wq_ * 8] = *(const uint4*)&w0h[(size_t)wn_ * 256 + kc + wq_ * 8];
        *(uint4*)&sWl[wn_ * TST + wq_ * 8] = *(const uint4*)&w0l[(size_t)wn_ * 256 + kc + wq_ * 8];
        __syncthreads();

        uint32_t fxh[2][4], fxl[2][4];
#pragma unroll
        for (int ks = 0; ks < 2; ks++) {       // accN pass: relu(x) @ w0
            LDSM4(fxh[ks][0], fxh[ks][1], fxh[ks][2], fxh[ks][3], aXh + akOff + ks * 32);
            LDSM4(fxl[ks][0], fxl[ks][1], fxl[ks][2], fxl[ks][3], aXl + akOff + ks * 32);
            uint32_t frh[4], frl[4];
#pragma unroll
            for (int i = 0; i < 4; i++) relu_mask(fxh[ks][i], fxl[ks][i], frh[i], frl[i]);
#pragma unroll
            for (int jn = 0; jn < 8; jn++) {
                uint32_t ba = bkOff + ks * 32 + jn * (8 * TST * 2);
                uint32_t p0, p1, q0, q1;
                LDSM2(p0, p1, aWh + ba);
                LDSM2(q0, q1, aWl + ba);
                MMA16816(accN + jn * 4, frh[0], frh[1], frh[2], frh[3], p0, p1);
                MMA16816(accN + jn * 4, frh[0], frh[1], frh[2], frh[3], q0, q1);
                MMA16816(accN + jn * 4, frl[0], frl[1], frl[2], frl[3], p0, p1);
            }
        }
        __syncthreads();
        *(uint4*)&sWh[wn_ * TST + wq_ * 8] = *(const uint4*)&wsh[(size_t)wn_ * 256 + kc + wq_ * 8];
        *(uint4*)&sWl[wn_ * TST + wq_ * 8] = *(const uint4*)&wsl[(size_t)wn_ * 256 + kc + wq_ * 8];
        __syncthreads();
#pragma unroll
        for (int ks = 0; ks < 2; ks++) {       // accS pass: x @ ws
#pragma unroll
            for (int jn = 0; jn < 8; jn++) {
                uint32_t ba = bkOff + ks * 32 + jn * (8 * TST * 2);
                uint32_t p0, p1, q0, q1;
                LDSM2(p0, p1, aWh + ba);
                LDSM2(q0, q1, aWl + ba);
                MMA16816(accS + jn * 4, fxh[ks][0], fxh[ks][1], fxh[ks][2], fxh[ks][3], p0, p1);
                MMA16816(accS + jn * 4, fxh[ks][0], fxh[ks][1], fxh[ks][2], fxh[ks][3], q0, q1);
                MMA16816(accS + jn * 4, fxl[ks][0], fxl[ks][1], fxl[ks][2], fxl[ks][3], p0, p1);
            }
        }
    }

    // ---------------- stage B: K = 128, 4 chunks of 32 ----------------------
    for (int kb = 0; kb < 4; kb++) {
        __syncthreads();
        if (wn == (kb >> 1) * 64) {            // owning col-warps write srelu
            int row0 = wm + (lane >> 2);
#pragma unroll
            for (int jj = 0; jj < 4; jj++) {
                int jn = (kb & 1) * 4 + jj;
                int c  = wn + (lane & 3) * 2 + jn * 8;
                int lc = jj * 8 + (lane & 3) * 2;
                float bv0 = b0[c], bv1 = b0[c + 1];
                float v00 = fmaxf(accN[jn * 4 + 0] + bv0, 0.0f);
                float v01 = fmaxf(accN[jn * 4 + 1] + bv1, 0.0f);
                float v10 = fmaxf(accN[jn * 4 + 2] + bv0, 0.0f);
                float v11 = fmaxf(accN[jn * 4 + 3] + bv1, 0.0f);
                __nv_bfloat162 h2, l2;
                split_hl(v00, h2.x, l2.x); split_hl(v01, h2.y, l2.y);
                *(__nv_bfloat162*)&sXh[row0 * TST + lc] = h2;
                *(__nv_bfloat162*)&sXl[row0 * TST + lc] = l2;
                split_hl(v10, h2.x, l2.x); split_hl(v11, h2.y, l2.y);
                *(__nv_bfloat162*)&sXh[(row0 + 8) * TST + lc] = h2;
                *(__nv_bfloat162*)&sXl[(row0 + 8) * TST + lc] = l2;
            }
        }
        *(uint4*)&sWh[wn_ * TST + wq_ * 8] = *(const uint4*)&w1h[(size_t)wn_ * 128 + kb * 32 + wq_ * 8];
        *(uint4*)&sWl[wn_ * TST + wq_ * 8] = *(const uint4*)&w1l[(size_t)wn_ * 128 + kb * 32 + wq_ * 8];
        __syncthreads();
#pragma unroll
        for (int ks = 0; ks < 2; ks++) {
            uint32_t fh[4], fl[4];
            LDSM4(fh[0], fh[1], fh[2], fh[3], aXh + akOff + ks * 32);
            LDSM4(fl[0], fl[1], fl[2], fl[3], aXl + akOff + ks * 32);
#pragma unroll
            for (int jn = 0; jn < 8; jn++) {
                uint32_t ba = bkOff + ks * 32 + jn * (8 * TST * 2);
                uint32_t p0, p1, q0, q1;
                LDSM2(p0, p1, aWh + ba);
                LDSM2(q0, q1, aWl + ba);
                MMA16816(accS + jn * 4, fh[0], fh[1], fh[2], fh[3], p0, p1);
                MMA16816(accS + jn * 4, fh[0], fh[1], fh[2], fh[3], q0, q1);
                MMA16816(accS + jn * 4, fl[0], fl[1], fl[2], fl[3], p0, p1);
            }
        }
    }

    // -------- epilogue: g_net = accS + b1 (+ fused scatter-max) -------------
    {
        int row0 = wm + (lane >> 2);
        int cb2 = wn + (lane & 3) * 2;
        size_t mA = m0 + row0, mB = mA + 8;
        unsigned* bo = (scatterSel == 1) ? g_binsB : g_binsA;
        size_t baseA[3], baseB[3];
        if (scatterSel >= 0) {
            int bA = (int)(mA >> 13), bB = (int)(mB >> 13);
#pragma unroll
            for (int p = 0; p < 3; p++) {
                baseA[p] = ((size_t)p * 131072 + bA * 16384 + g_idx[p * 65536 + (int)mA]) * 128;
                baseB[p] = ((size_t)p * 131072 + bB * 16384 + g_idx[p * 65536 + (int)mB]) * 128;
            }
        }
#pragma unroll
        for (int jn = 0; jn < 8; jn++) {
            int c = cb2 + jn * 8;
            float bv0 = b1[c], bv1 = b1[c + 1];
            float2 v0 = make_float2(accS[jn * 4 + 0] + bv0, accS[jn * 4 + 1] + bv1);
            float2 v1 = make_float2(accS[jn * 4 + 2] + bv0, accS[jn * 4 + 3] + bv1);
            *(float2*)&g_net[mA * 128 + c] = v0;
            *(float2*)&g_net[mB * 128 + c] = v1;
            if (scatterSel >= 0) {
                unsigned k0x = f2ord(v0.x), k0y = f2ord(v0.y);
                unsigned k1x = f2ord(v1.x), k1y = f2ord(v1.y);
#pragma unroll
                for (int p = 0; p < 3; p++) {
                    atomicMax(&bo[baseA[p] + c], k0x);
                    atomicMax(&bo[baseA[p] + c + 1], k0y);
                    atomicMax(&bo[baseB[p] + c], k1x);
                    atomicMax(&bo[baseB[p] + c + 1], k1y);
                }
            }
        }
    }
}

// ------------------------- final fc (mma.sync) + fused plane scatter --------
__global__ void __launch_bounds__(512)
k_fc_mma(int selx, int woff, const float* __restrict__ b, int scatterSel, int doCount)
{
    __shared__ __nv_bfloat16 sXh[128 * TST], sXl[128 * TST];
    __shared__ __nv_bfloat16 sWh[128 * TST], sWl[128 * TST];
    const uint32_t aXh = smem_u32(sXh), aXl = smem_u32(sXl);
    const uint32_t aWh = smem_u32(sWh), aWl = smem_u32(sWl);

    const int tid = threadIdx.x, wid = tid >> 5, lane = tid & 31;
    const int wm = (wid >> 1) * 16;
    const int wn = (wid & 1) * 64;
    const size_t m0 = (size_t)blockIdx.x * 128;

    const float* x = bufptr(selx);
    const __nv_bfloat16* wh = g_wt + woff;   // [128][128]
    const __nv_bfloat16* wl = wh + 16384;

    float acc[32];
#pragma unroll
    for (int i = 0; i < 32; i++) acc[i] = 0.0f;

    const uint32_t akOff = (uint32_t)((wm + (lane & 15)) * TST + ((lane >> 4) & 1) * 8) * 2;
    const uint32_t bkOff = (uint32_t)((wn + (lane & 7)) * TST + ((lane >> 3) & 1) * 8) * 2;
    const int wn_ = tid >> 2, wq_ = tid & 3;

    for (int kc = 0; kc < 128; kc += 32) {
        __syncthreads();
#pragma unroll
        for (int it = 0; it < 4; it++) {
            int e = it * 512 + tid;
            int r = e >> 4, cp = e & 15;
            float2 v = *(const float2*)&x[(m0 + r) * 128 + kc + cp * 2];
            __nv_bfloat162 h2, l2;
            split_hl(v.x, h2.x, l2.x);
            split_hl(v.y, h2.y, l2.y);
            int o = r * TST + cp * 2;
            *(__nv_bfloat162*)&sXh[o] = h2;
            *(__nv_bfloat162*)&sXl[o] = l2;
        }
        *(uint4*)&sWh[wn_ * TST + wq_ * 8] = *(const uint4*)&wh[(size_t)wn_ * 128 + kc + wq_ * 8];
        *(uint4*)&sWl[wn_ * TST + wq_ * 8] = *(const uint4*)&wl[(size_t)wn_ * 128 + kc + wq_ * 8];
        __syncthreads();
#pragma unroll
        for (int ks = 0; ks < 2; ks++) {
            uint32_t fh[4], fl[4];
            LDSM4(fh[0], fh[1], fh[2], fh[3], aXh + akOff + ks * 32);
            LDSM4(fl[0], fl[1], fl[2], fl[3], aXl + akOff + ks * 32);
#pragma unroll
            for (int jn = 0; jn < 8; jn++) {
                uint32_t ba = bkOff + ks * 32 + jn * (8 * TST * 2);
                uint32_t p0, p1, q0, q1;
                LDSM2(p0, p1, aWh + ba);
                LDSM2(q0, q1, aWl + ba);
                MMA16816(acc + jn * 4, fh[0], fh[1], fh[2], fh[3], p0, p1);
                MMA16816(acc + jn * 4, fh[0], fh[1], fh[2], fh[3], q0, q1);
                MMA16816(acc + jn * 4, fl[0], fl[1], fl[2], fl[3], p0, p1);
            }
        }
    }

    // epilogue: scatter-add c values into plane-sum bins (+ counts once)
    {
        float* so = (float*)((scatterSel == 1) ? g_binsB : g_binsA);
        int row0 = wm + (lane >> 2);
        int cb2 = wn + (lane & 3) * 2;
        size_t mA = m0 + row0, mB = mA + 8;
        int bA = (int)(mA >> 13), bB = (int)(mB >> 13);
        int binA[3], binB[3];
        size_t baseA[3], baseB[3];
#pragma unroll
        for (int p = 0; p < 3; p++) {
            binA[p] = g_idx[p * 65536 + (int)mA];
            binB[p] = g_idx[p * 65536 + (int)mB];
            baseA[p] = ((size_t)p * 131072 + bA * 16384 + binA[p]) * 128;
            baseB[p] = ((size_t)p * 131072 + bB * 16384 + binB[p]) * 128;
        }
#pragma unroll
        for (int jn = 0; jn < 8; jn++) {
            int c = cb2 + jn * 8;
            float bv0 = b[c], bv1 = b[c + 1];
            float v0x = acc[jn * 4 + 0] + bv0, v0y = acc[jn * 4 + 1] + bv1;
            float v1x = acc[jn * 4 + 2] + bv0, v1y = acc[jn * 4 + 3] + bv1;
#pragma unroll
            for (int p = 0; p < 3; p++) {
                atomicAdd(&so[baseA[p] + c], v0x);
                atomicAdd(&so[baseA[p] + c + 1], v0y);
                atomicAdd(&so[baseB[p] + c], v1x);
                atomicAdd(&so[baseB[p] + c + 1], v1y);
            }
        }
        if (doCount && wn == 0 && (lane & 3) == 0) {
#pragma unroll
            for (int p = 0; p < 3; p++) {
                atomicAdd(&g_cnt[p * 131072 + bA * 16384 + binA[p]], 1.0f);
                atomicAdd(&g_cnt[p * 131072 + bB * 16384 + binB[p]], 1.0f);
            }
        }
    }
}

// ------------------------- plane mean writeback -----------------------------
__global__ void k_transpose_div(float* __restrict__ outb, int po, int binsSel) {
    __shared__ float t[32][33];
    int p = blockIdx.z >> 3, b = blockIdx.z & 7;
    int bin0 = blockIdx.x * 32, c0 = blockIdx.y * 32;
    const float* sums = (const float*)(binsSel ? g_binsB : g_binsA);
    size_t base = (size_t)p * 131072 + (size_t)b * 16384;
#pragma unroll
    for (int i = 0; i < 4; i++)
        t[threadIdx.y + 8 * i][threadIdx.x] =
            sums[(base + bin0 + threadIdx.y + 8 * i) * 128 + c0 + threadIdx.x];
    __syncthreads();
    float cv = fmaxf(g_cnt[base + bin0 + threadIdx.x], 1.0f);
#pragma unroll
    for (int i = 0; i < 4; i++) {
        int c = c0 + threadIdx.y + 8 * i;
        outb[(((size_t)(p + po) * 8 + b) * 128 + c) * 16384 + bin0 + threadIdx.x] =
            t[threadIdx.x][threadIdx.y + 8 * i] / cv;
    }
}

// ------------------------- driver -------------------------------------------
static inline int wt_off_blk(int s, int i) { return (s * 5 + i) * 163840; }

extern "C" void kernel_launch(void* const* d_in, const int* in_sizes, int n_in,
                              void* d_out, int out_size) {
    const float* p      = (const float*)d_in[0];
    const float* p2     = (const float*)d_in[1];
    const float* wp     = (const float*)d_in[2];
    const float* bp     = (const float*)d_in[3];
    const float* wp2    = (const float*)d_in[4];
    const float* bp2    = (const float*)d_in[5];
    const float* blk_w0 = (const float*)d_in[6];
    const float* blk_b0 = (const float*)d_in[7];
    const float* blk_w1 = (const float*)d_in[8];
    const float* blk_b1 = (const float*)d_in[9];
    const float* blk_ws = (const float*)d_in[10];
    const float* blkc_w0= (const float*)d_in[11];
    const float* blkc_b0= (const float*)d_in[12];
    const float* blkc_w1= (const float*)d_in[13];
    const float* blkc_b1= (const float*)d_in[14];
    const float* blkc_ws= (const float*)d_in[15];
    const float* fc_c_w = (const float*)d_in[16];
    const float* fc_c_b = (const float*)d_in[17];
    const float* fc_cc_w= (const float*)d_in[18];
    const float* fc_cc_b= (const float*)d_in[19];
    float* out = (float*)d_out;

    k_clear_bins<<<49152, 256>>>(0);
    k_init<<<65536, 256>>>(p, p2, wp, bp, wp2, bp2);
    k_prep_all<<<3328, 256>>>(blk_w0, blk_w1, blk_ws,
                              blkc_w0, blkc_w1, blkc_ws, fc_c_w, fc_cc_w);

    // stream 0: alternate bins A(0)/B(1)
    k_resblock_mma<<<512, 512>>>(0, 256, 0, 0, 256, 128, -1, 0,
                                 wt_off_blk(0, 0), blk_b0, blk_b1);
    k_clear_bins<<<49152, 256>>>(1);
    k_resblock_mma<<<512, 512>>>(2, 128, 0, 2, 128, 0, 0, 1,
                                 wt_off_blk(0, 1), blk_b0 + 128, blk_b1 + 128);
    k_clear_bins<<<49152, 256>>>(0);
    k_resblock_mma<<<512, 512>>>(2, 128, 0, 2, 128, 0, 1, 0,
                                 wt_off_blk(0, 2), blk_b0 + 256, blk_b1 + 256);
    k_clear_bins<<<49152, 256>>>(1);
    k_resblock_mma<<<512, 512>>>(2, 128, 0, 2, 128, 0, 0, 1,
                                 wt_off_blk(0, 3), blk_b0 + 384, blk_b1 + 384);
    k_resblock_mma<<<512, 512>>>(2, 128, 0, 2, 128, 0, 1, -1,
                                 wt_off_blk(0, 4), blk_b0 + 512, blk_b1 + 512);
    k_clear_bins<<<49152, 256>>>(0);
    k_clear_cnt<<<1536, 256>>>();
    k_fc_mma<<<512, 512>>>(2, 1638400, fc_c_b, 0, 1);
    k_transpose_div<<<dim3(512, 4, 24), dim3(32, 8)>>>(out, 0, 0);

    // stream 1
    k_clear_bins<<<49152, 256>>>(1);
    k_resblock_mma<<<512, 512>>>(1, 256, 0, 1, 256, 128, -1, 1,
                                 wt_off_blk(1, 0), blkc_b0, blkc_b1);
    k_clear_bins<<<49152, 256>>>(0);
    k_resblock_mma<<<512, 512>>>(2, 128, 0, 2, 128, 0, 1, 0,
                                 wt_off_blk(1, 1), blkc_b0 + 128, blkc_b1 + 128);
    k_clear_bins<<<49152, 256>>>(1);
    k_resblock_mma<<<512, 512>>>(2, 128, 0, 2, 128, 0, 0, 1,
                                 wt_off_blk(1, 2), blkc_b0 + 256, blkc_b1 + 256);
    k_clear_bins<<<49152, 256>>>(0);
    k_resblock_mma<<<512, 512>>>(2, 128, 0, 2, 128, 0, 1, 0,
                                 wt_off_blk(1, 3), blkc_b0 + 384, blkc_b1 + 384);
    k_resblock_mma<<<512, 512>>>(2, 128, 0, 2, 128, 0, 0, -1,
                                 wt_off_blk(1, 4), blkc_b0 + 512, blkc_b1 + 512);
    k_clear_bins<<<49152, 256>>>(1);
    k_fc_mma<<<512, 512>>>(2, 1671168, fc_cc_b, 1, 0);
    k_transpose_div<<<dim3(512, 4, 24), dim3(32, 8)>>>(out, 3, 1);
}